// round 2
// baseline (speedup 1.0000x reference)
#include <cuda_runtime.h>
#include <cstdint>
#include <math.h>

#define LSEQ 2304
#define DIMC 192
#define EC   384
#define NC   16
#define PC   64
#define HHC  6
#define KC   4
#define ROWS (KC*LSEQ)   /* 9216 */
#define ZXW  806         /* 768 (zx) + 32 (bc) + 6 (dt) */

// ---------------- scratch (static device globals; no allocation) ----------------
static __device__ float g_xseq[ROWS*DIMC];
static __device__ float g_proj[ROWS*768];
static __device__ float g_xssm[ROWS*EC];
static __device__ float g_wcomb[EC*ZXW];
static __device__ float g_zx[(size_t)ROWS*ZXW];
static __device__ float g_dtb[ROWS*HHC];
static __device__ float g_rb[ROWS*HHC];
static __device__ float g_cum[ROWS*HHC];
static __device__ float g_Bt[ROWS*HHC*NC];
static __device__ float g_Ct[ROWS*HHC*NC];
static __device__ float g_y[ROWS*EC];
static __device__ float g_g[ROWS*EC];
static __device__ float g_mo[ROWS*EC];
static __device__ float g_xout[ROWS*EC];
static __device__ float g_mT[LSEQ*EC];
static __device__ float g_pre[LSEQ*DIMC];

__device__ __forceinline__ float siluf(float v){ return v / (1.f + expf(-v)); }

// ---------------- K0: build 4-direction sequence ----------------
// CRITICAL: reference does xs.reshape(Bn*K, L, DIM) — a flat memory
// REINTERPRETATION of each (DIM, L) plane as (L, DIM), not a transpose.
// So x_seq flat offset within plane k equals the plane's own flat offset;
// we only apply the direction map to the plane-internal l index.
__global__ void k_build(const float* __restrict__ x, float* __restrict__ xseq){
    int idx = blockIdx.x*blockDim.x + threadIdx.x;
    if (idx >= ROWS*DIMC) return;
    int k   = idx / (LSEQ*DIMC);
    int off = idx % (LSEQ*DIMC);   // flat offset inside the (DIM,L) plane
    int d   = off / LSEQ;
    int l   = off % LSEQ;
    int m;
    if      (k==0) m = l;
    else if (k==1) m = (l%48)*48 + l/48;
    else if (k==2) m = 2303 - l;
    else { int lr = 2303-l; m = (lr%48)*48 + lr/48; }
    xseq[idx] = x[d*LSEQ + m];
}

// ---------------- generic fp32 GEMM: C[M,N] = A[M,K] @ B[K,N] ----------------
// Requirements here: M % 128 == 0, K % 16 == 0 (true for all calls). N arbitrary.
__global__ __launch_bounds__(256) void k_gemm(const float* __restrict__ A,
                                              const float* __restrict__ B,
                                              float* __restrict__ C,
                                              int M, int N, int K){
    const int BM=128, BN=64, BK=16;
    __shared__ __align__(16) float As[BK][BM];
    __shared__ __align__(16) float Bs[BK][BN];
    int tx = threadIdx.x & 15;   // n dir (16 * TN=4 = 64)
    int ty = threadIdx.x >> 4;   // m dir (16 * TM=8 = 128)
    int bm = blockIdx.y*BM, bn = blockIdx.x*BN;
    float acc[8][4];
    #pragma unroll
    for (int m=0;m<8;m++)
        #pragma unroll
        for (int n=0;n<4;n++) acc[m][n]=0.f;

    for (int k0=0; k0<K; k0+=BK){
        #pragma unroll
        for (int i=threadIdx.x; i<BM*BK; i+=256){
            int r = i>>4, c = i&15;
            As[c][r] = A[(size_t)(bm+r)*K + k0 + c];
        }
        #pragma unroll
        for (int i=threadIdx.x; i<BK*BN; i+=256){
            int r = i>>6, c = i&63;
            int col = bn + c;
            Bs[r][c] = (col < N) ? B[(size_t)(k0+r)*N + col] : 0.f;
        }
        __syncthreads();
        #pragma unroll
        for (int kk=0; kk<BK; kk++){
            float4 b4 = *reinterpret_cast<const float4*>(&Bs[kk][tx*4]);
            float4 a0 = *reinterpret_cast<const float4*>(&As[kk][ty*8]);
            float4 a1 = *reinterpret_cast<const float4*>(&As[kk][ty*8+4]);
            float a[8] = {a0.x,a0.y,a0.z,a0.w,a1.x,a1.y,a1.z,a1.w};
            float b[4] = {b4.x,b4.y,b4.z,b4.w};
            #pragma unroll
            for (int m=0;m<8;m++)
                #pragma unroll
                for (int n=0;n<4;n++) acc[m][n] = fmaf(a[m], b[n], acc[m][n]);
        }
        __syncthreads();
    }
    #pragma unroll
    for (int m=0;m<8;m++){
        int row = bm + ty*8 + m;
        #pragma unroll
        for (int n=0;n<4;n++){
            int col = bn + tx*4 + n;
            if (col < N) C[(size_t)row*N + col] = acc[m][n];
        }
    }
}

// ---------------- epilogue: x_ssm = silu(proj[:, :384]) ----------------
__global__ void k_silu_ssm(const float* __restrict__ proj, float* __restrict__ xssm){
    int idx = blockIdx.x*blockDim.x + threadIdx.x;
    if (idx >= ROWS*EC) return;
    int row = idx / EC, e = idx % EC;
    float v = proj[(size_t)row*768 + e];
    xssm[idx] = siluf(v);
}

// ---------------- build combined weight [w_zx | w_bc | w_dt] ----------------
__global__ void k_wcomb(const float* __restrict__ wzx, const float* __restrict__ wbc,
                        const float* __restrict__ wdt, float* __restrict__ wc){
    int idx = blockIdx.x*blockDim.x + threadIdx.x;
    if (idx >= EC*ZXW) return;
    int kk = idx / ZXW, j = idx % ZXW;
    float v;
    if (j < 768)      v = wzx[kk*768 + j];
    else if (j < 800) v = wbc[kk*32 + (j-768)];
    else              v = wdt[kk*6 + (j-800)];
    wc[idx] = v;
}

// ---------------- dt = softplus(..+bias), r = exp(-dt*exp(A_log)), cumsum(dt) ----------------
// one block per (k,h): 24 blocks x 256 threads, 9 elements/thread
__global__ void k_dtscan(const float* __restrict__ zx, const float* __restrict__ dt_bias,
                         const float* __restrict__ A_log,
                         float* __restrict__ dtb, float* __restrict__ rb, float* __restrict__ cumb){
    int k = blockIdx.x / HHC, h = blockIdx.x % HHC;
    __shared__ float part[256];
    float expA = expf(A_log[h]);
    float bias = dt_bias[h];
    int tid = threadIdx.x;
    int tbase = tid*9;
    float loc[9]; float s = 0.f;
    #pragma unroll
    for (int i=0;i<9;i++){
        size_t row = (size_t)k*LSEQ + tbase + i;
        float v  = zx[row*ZXW + 800 + h] + bias;
        float dt = (v > 20.f) ? v : log1pf(expf(v));
        dtb[row*HHC+h] = dt;
        rb [row*HHC+h] = expf(-dt*expA);
        s += dt; loc[i] = s;
    }
    part[tid] = s; __syncthreads();
    for (int off=1; off<256; off<<=1){
        float add = (tid >= off) ? part[tid-off] : 0.f;
        __syncthreads();
        part[tid] += add;
        __syncthreads();
    }
    float offset = part[tid] - s;
    #pragma unroll
    for (int i=0;i<9;i++){
        size_t row = (size_t)k*LSEQ + tbase + i;
        cumb[row*HHC+h] = loc[i] + offset;
    }
}

// ---------------- rms(B/C) + rotary -> Bt, Ct  (thread per (k,t)) ----------------
__global__ void k_rot(const float* __restrict__ zx, const float* __restrict__ b_bc,
                      const float* __restrict__ theta, const float* __restrict__ cumb,
                      float* __restrict__ Bt, float* __restrict__ Ct){
    int row = blockIdx.x*blockDim.x + threadIdx.x;
    if (row >= ROWS) return;
    const float* bc = zx + (size_t)row*ZXW + 768;
    float b[16], c[16];
    float sb = 0.f, sc = 0.f;
    #pragma unroll
    for (int i=0;i<16;i++){ b[i] = bc[i]    + b_bc[i];    sb += b[i]*b[i]; }
    #pragma unroll
    for (int i=0;i<16;i++){ c[i] = bc[16+i] + b_bc[16+i]; sc += c[i]*c[i]; }
    float rB = rsqrtf(sb*(1.f/16.f) + 1e-6f);
    float rC = rsqrtf(sc*(1.f/16.f) + 1e-6f);
    #pragma unroll
    for (int h=0; h<HHC; h++){
        float cd = cumb[(size_t)row*HHC + h];
        float* Bo = Bt + ((size_t)row*HHC + h)*16;
        float* Co = Ct + ((size_t)row*HHC + h)*16;
        #pragma unroll
        for (int i=0;i<8;i++){
            float ss, cc;
            sincosf(cd*theta[h*8+i], &ss, &cc);
            float v0 = b[2*i]*rB, v1 = b[2*i+1]*rB;
            Bo[2*i]   =  v0*cc + v1*ss;
            Bo[2*i+1] = -v0*ss + v1*cc;
            v0 = c[2*i]*rC; v1 = c[2*i+1]*rC;
            Co[2*i]   =  v0*cc + v1*ss;
            Co[2*i+1] = -v0*ss + v1*cc;
        }
    }
}

// ---------------- sequential selective scan ----------------
// grid (24 = k*6+h, 4 = p-split), 256 threads: tid = p_local*16 + n
__global__ __launch_bounds__(256) void k_scan(const float* __restrict__ Bt, const float* __restrict__ Ct,
                                              const float* __restrict__ zx, const float* __restrict__ dtb,
                                              const float* __restrict__ rb, const float* __restrict__ Dsk,
                                              float* __restrict__ y){
    int kh = blockIdx.x; int k = kh/HHC, h = kh%HHC;
    int n = threadIdx.x & 15;
    int p = (blockIdx.y << 4) + (threadIdx.x >> 4);
    size_t rowB = ((size_t)k*LSEQ*HHC + h)*16 + n;   // Bt/Ct index, stride 96 per t
    size_t rowX = (size_t)k*LSEQ*ZXW + 384 + h*64 + p; // xh in zx, stride 806 per t
    size_t rowS = (size_t)k*LSEQ*HHC + h;            // dt/r, stride 6 per t
    float dsk = Dsk[h];
    float* yout = y + (size_t)k*LSEQ*EC + h*64 + p;
    float hs = 0.f, Bp = 0.f, xp = 0.f;
    float Bc = Bt[rowB], Cc = Ct[rowB], xc = zx[rowX], dtc = dtb[rowS], rc = rb[rowS];
    for (int t=0; t<LSEQ; ++t){
        float Bn2=0.f, Cn2=0.f, xn2=0.f, dtn2=0.f, rn2=0.f;
        if (t+1 < LSEQ){
            Bn2 = Bt[rowB+96]; Cn2 = Ct[rowB+96]; xn2 = zx[rowX+ZXW];
            dtn2 = dtb[rowS+HHC]; rn2 = rb[rowS+HHC];
        }
        float inp = 0.5f*dtc*(Bc*xc + rc*Bp*xp);
        hs = fmaf(rc, hs, inp);
        float v = Cc*hs;
        v += __shfl_xor_sync(0xffffffffu, v, 8);
        v += __shfl_xor_sync(0xffffffffu, v, 4);
        v += __shfl_xor_sync(0xffffffffu, v, 2);
        v += __shfl_xor_sync(0xffffffffu, v, 1);
        if (n == 0) yout[(size_t)t*EC] = v + dsk*xc;
        Bp = Bc; xp = xc;
        Bc = Bn2; Cc = Cn2; xc = xn2; dtc = dtn2; rc = rn2;
        rowB += 96; rowX += ZXW; rowS += HHC;
    }
}

// ---------------- g = rms(y * silu(z)) * rms_w  (warp per row) ----------------
__global__ void k_gate(const float* __restrict__ y, const float* __restrict__ zx,
                       const float* __restrict__ rms_w, float* __restrict__ g){
    int warp = (blockIdx.x*blockDim.x + threadIdx.x) >> 5;
    int lane = threadIdx.x & 31;
    if (warp >= ROWS) return;
    size_t ybase = (size_t)warp*EC;
    size_t zbase = (size_t)warp*ZXW;
    float v[12]; float s2 = 0.f;
    #pragma unroll
    for (int j=0;j<12;j++){
        int e = lane + j*32;
        float z = zx[zbase + e];
        float t = y[ybase + e] * siluf(z);
        v[j] = t; s2 += t*t;
    }
    #pragma unroll
    for (int off=16; off>=1; off>>=1) s2 += __shfl_xor_sync(0xffffffffu, s2, off);
    float rn = rsqrtf(s2*(1.f/384.f) + 1e-6f);
    #pragma unroll
    for (int j=0;j<12;j++){
        int e = lane + j*32;
        g[ybase + e] = v[j]*rn*rms_w[e];
    }
}

// ---------------- x_out = mamba_out * silu(x_gate) ----------------
__global__ void k_xout(const float* __restrict__ mo, const float* __restrict__ proj,
                       float* __restrict__ xout){
    int idx = blockIdx.x*blockDim.x + threadIdx.x;
    if (idx >= ROWS*EC) return;
    int row = idx / EC, e = idx % EC;
    float gv = proj[(size_t)row*768 + 384 + e];
    xout[idx] = mo[idx] * siluf(gv);
}

// ---------------- merge 4 directions -> mergedT[l][e] ----------------
__global__ void k_merge(const float* __restrict__ xout, float* __restrict__ mT){
    int idx = blockIdx.x*blockDim.x + threadIdx.x;
    if (idx >= LSEQ*EC) return;
    int l = idx / EC, e = idx % EC;
    int lt = (l%48)*48 + l/48;
    float v = xout[(size_t)l*EC + e]
            + xout[(size_t)(LSEQ + lt)*EC + e]
            + xout[(size_t)(2*LSEQ + 2303 - l)*EC + e]
            + xout[(size_t)(3*LSEQ + 2303 - lt)*EC + e];
    mT[idx] = v;
}

// ---------------- LayerNorm (over DIM per spatial) + residual ----------------
__global__ void k_ln(const float* __restrict__ pre, const float* __restrict__ x,
                     const float* __restrict__ ln_g, const float* __restrict__ ln_b,
                     const float* __restrict__ res_scale, float* __restrict__ out){
    int warp = (blockIdx.x*blockDim.x + threadIdx.x) >> 5;
    int lane = threadIdx.x & 31;
    if (warp >= LSEQ) return;
    int l = warp;
    float v[6]; float s = 0.f;
    #pragma unroll
    for (int j=0;j<6;j++){ v[j] = pre[(size_t)l*DIMC + lane + j*32]; s += v[j]; }
    #pragma unroll
    for (int off=16; off>=1; off>>=1) s += __shfl_xor_sync(0xffffffffu, s, off);
    float mu = s*(1.f/192.f);
    float q = 0.f;
    #pragma unroll
    for (int j=0;j<6;j++){ float d = v[j]-mu; q += d*d; }
    #pragma unroll
    for (int off=16; off>=1; off>>=1) q += __shfl_xor_sync(0xffffffffu, q, off);
    float inv = rsqrtf(q*(1.f/192.f) + 1e-5f);
    float rs = res_scale[0];
    #pragma unroll
    for (int j=0;j<6;j++){
        int d = lane + j*32;
        out[(size_t)d*LSEQ + l] = x[(size_t)d*LSEQ + l]
            + rs*((v[j]-mu)*inv*ln_g[d] + ln_b[d]);
    }
}

// ---------------- launch ----------------
extern "C" void kernel_launch(void* const* d_in, const int* in_sizes, int n_in,
                              void* d_out, int out_size){
    (void)in_sizes; (void)n_in; (void)out_size;
    const float* x        = (const float*)d_in[0];
    const float* w_in     = (const float*)d_in[1];
    const float* w_zx     = (const float*)d_in[2];
    const float* w_bc     = (const float*)d_in[3];
    const float* b_bc     = (const float*)d_in[4];
    const float* w_dt     = (const float*)d_in[5];
    const float* dt_bias  = (const float*)d_in[6];
    const float* A_log    = (const float*)d_in[7];
    const float* theta    = (const float*)d_in[8];
    const float* D_skip   = (const float*)d_in[9];
    const float* rms_w    = (const float*)d_in[10];
    const float* w_mout   = (const float*)d_in[11];
    const float* w_out    = (const float*)d_in[12];
    const float* ln_g     = (const float*)d_in[13];
    const float* ln_b     = (const float*)d_in[14];
    const float* resscale = (const float*)d_in[15];
    float* out = (float*)d_out;

    float *b_xseq, *b_proj, *b_xssm, *b_wcomb, *b_zx, *b_dtb, *b_rb, *b_cum;
    float *b_Bt, *b_Ct, *b_y, *b_g, *b_mo, *b_xout, *b_mT, *b_pre;
    cudaGetSymbolAddress((void**)&b_xseq, g_xseq);
    cudaGetSymbolAddress((void**)&b_proj, g_proj);
    cudaGetSymbolAddress((void**)&b_xssm, g_xssm);
    cudaGetSymbolAddress((void**)&b_wcomb, g_wcomb);
    cudaGetSymbolAddress((void**)&b_zx,   g_zx);
    cudaGetSymbolAddress((void**)&b_dtb,  g_dtb);
    cudaGetSymbolAddress((void**)&b_rb,   g_rb);
    cudaGetSymbolAddress((void**)&b_cum,  g_cum);
    cudaGetSymbolAddress((void**)&b_Bt,   g_Bt);
    cudaGetSymbolAddress((void**)&b_Ct,   g_Ct);
    cudaGetSymbolAddress((void**)&b_y,    g_y);
    cudaGetSymbolAddress((void**)&b_g,    g_g);
    cudaGetSymbolAddress((void**)&b_mo,   g_mo);
    cudaGetSymbolAddress((void**)&b_xout, g_xout);
    cudaGetSymbolAddress((void**)&b_mT,   g_mT);
    cudaGetSymbolAddress((void**)&b_pre,  g_pre);

    // 0: direction sequences (memory-reinterpret semantics, see k_build)
    k_build<<<(ROWS*DIMC+255)/256, 256>>>(x, b_xseq);
    // 1: proj = x_seq @ w_in  (9216 x 768 x 192)
    k_gemm<<<dim3(768/64, ROWS/128), 256>>>(b_xseq, w_in, b_proj, ROWS, 768, DIMC);
    // 2: silu of ssm half
    k_silu_ssm<<<(ROWS*EC+255)/256, 256>>>(b_proj, b_xssm);
    // 3: combined weight + zx/bc/dt GEMM (9216 x 806 x 384)
    k_wcomb<<<(EC*ZXW+255)/256, 256>>>(w_zx, w_bc, w_dt, b_wcomb);
    k_gemm<<<dim3((ZXW+63)/64, ROWS/128), 256>>>(b_xssm, b_wcomb, b_zx, ROWS, ZXW, EC);
    // 4: dt / r / cumsum(dt)
    k_dtscan<<<KC*HHC, 256>>>(b_zx, dt_bias, A_log, b_dtb, b_rb, b_cum);
    // 5: rms + rotary for B and C
    k_rot<<<(ROWS+127)/128, 128>>>(b_zx, b_bc, theta, b_cum, b_Bt, b_Ct);
    // 6: sequential scan -> y (+ D_skip * xh)
    k_scan<<<dim3(KC*HHC, 4), 256>>>(b_Bt, b_Ct, b_zx, b_dtb, b_rb, D_skip, b_y);
    // 7: gated rms norm
    k_gate<<<(ROWS*32+255)/256, 256>>>(b_y, b_zx, rms_w, b_g);
    // 8: mamba out GEMM (9216 x 384 x 384)
    k_gemm<<<dim3(EC/64, ROWS/128), 256>>>(b_g, w_mout, b_mo, ROWS, EC, EC);
    // 9: gate multiply
    k_xout<<<(ROWS*EC+255)/256, 256>>>(b_mo, b_proj, b_xout);
    // 10: merge 4 directions
    k_merge<<<(LSEQ*EC+255)/256, 256>>>(b_xout, b_mT);
    // 11: output projection GEMM (2304 x 192 x 384)
    k_gemm<<<dim3(DIMC/64, LSEQ/128), 256>>>(b_mT, w_out, b_pre, LSEQ, DIMC, EC);
    // 12: layernorm + residual -> d_out
    k_ln<<<(LSEQ*32+255)/256, 256>>>(b_pre, x, ln_g, ln_b, resscale, out);
}

// round 3
// speedup vs baseline: 1.2363x; 1.2363x over previous
#include <cuda_runtime.h>
#include <cstdint>
#include <math.h>

#define LSEQ 2304
#define DIMC 192
#define EC   384
#define NC   16
#define PC   64
#define HHC  6
#define KC   4
#define ROWS (KC*LSEQ)   /* 9216 */
#define ZXW  800         /* 768 (zx) + 32 (bc); dt handled separately in fp32 */

// ---------------- scratch (static device globals; no allocation) ----------------
static __device__ float g_xseq[ROWS*DIMC];
static __device__ float g_proj[ROWS*768];
static __device__ float g_xssm[ROWS*EC];
static __device__ float g_wcomb[EC*ZXW];
static __device__ float g_zx[(size_t)ROWS*ZXW];
static __device__ float g_dtr[ROWS*HHC];
static __device__ float g_dtb[ROWS*HHC];
static __device__ float g_rb[ROWS*HHC];
static __device__ float g_cum[ROWS*HHC];
static __device__ float g_Bt[ROWS*HHC*NC];
static __device__ float g_Ct[ROWS*HHC*NC];
static __device__ float g_y[ROWS*EC];
static __device__ float g_g[ROWS*EC];
static __device__ float g_mo[ROWS*EC];
static __device__ float g_xout[ROWS*EC];
static __device__ float g_mT[LSEQ*EC];
static __device__ float g_pre[LSEQ*DIMC];

__device__ __forceinline__ float siluf(float v){ return v / (1.f + expf(-v)); }

__device__ __forceinline__ uint32_t f2tf32(float f){
    uint32_t u; asm("cvt.rna.tf32.f32 %0, %1;" : "=r"(u) : "f"(f)); return u;
}

// ---------------- K0: build 4-direction sequence ----------------
// Reference does xs.reshape(Bn*K, L, DIM) — a flat memory REINTERPRETATION of
// each (DIM, L) plane as (L, DIM). Flat offset preserved; only direction map on l.
__global__ void k_build(const float* __restrict__ x, float* __restrict__ xseq){
    int idx = blockIdx.x*blockDim.x + threadIdx.x;
    if (idx >= ROWS*DIMC) return;
    int k   = idx / (LSEQ*DIMC);
    int off = idx % (LSEQ*DIMC);
    int d   = off / LSEQ;
    int l   = off % LSEQ;
    int m;
    if      (k==0) m = l;
    else if (k==1) m = (l%48)*48 + l/48;
    else if (k==2) m = 2303 - l;
    else { int lr = 2303-l; m = (lr%48)*48 + lr/48; }
    xseq[idx] = x[d*LSEQ + m];
}

// ---------------- tf32 tensor-core GEMM: C[M,N] = A[M,K] @ B[K,N] ----------------
// A,B,C row-major fp32 in gmem; converted to tf32 (cvt.rna) at smem store.
// Requirements: M % 128 == 0, K % 16 == 0. N arbitrary (guarded).
// 256 threads = 8 warps in 4(m) x 2(n); warp tile 32x32; mma m16n8k8.
__global__ __launch_bounds__(256) void k_gemm_tf32(const float* __restrict__ A,
                                                   const float* __restrict__ B,
                                                   float* __restrict__ C,
                                                   int M, int N, int K){
    const int BM=128, BN=64, BK=16;
    __shared__ uint32_t As[BK][BM+4];
    __shared__ uint32_t Bs[BK][BN+4];
    int tid  = threadIdx.x;
    int warp = tid>>5, lane = tid&31;
    int wm = warp>>1, wn = warp&1;       // 4 x 2 warp grid
    int gid = lane>>2, tig = lane&3;
    int bm = blockIdx.y*BM, bn = blockIdx.x*BN;

    float acc[2][4][4];
    #pragma unroll
    for (int m=0;m<2;m++)
        #pragma unroll
        for (int n=0;n<4;n++)
            #pragma unroll
            for (int i=0;i<4;i++) acc[m][n][i]=0.f;

    for (int k0=0; k0<K; k0+=BK){
        // A tile: 128x16, each thread 8 floats (two float4) from one row
        {
            int r  = tid>>1;
            int ch = (tid&1)*8;
            const float4* src = reinterpret_cast<const float4*>(&A[(size_t)(bm+r)*K + k0 + ch]);
            float4 v0 = src[0], v1 = src[1];
            As[ch+0][r]=f2tf32(v0.x); As[ch+1][r]=f2tf32(v0.y);
            As[ch+2][r]=f2tf32(v0.z); As[ch+3][r]=f2tf32(v0.w);
            As[ch+4][r]=f2tf32(v1.x); As[ch+5][r]=f2tf32(v1.y);
            As[ch+6][r]=f2tf32(v1.z); As[ch+7][r]=f2tf32(v1.w);
        }
        // B tile: 16x64, each thread 4 scalars (col-guarded)
        #pragma unroll
        for (int j=0;j<4;j++){
            int i = tid + j*256;
            int r = i>>6, c = i&63;
            int col = bn + c;
            float v = (col < N) ? B[(size_t)(k0+r)*N + col] : 0.f;
            Bs[r][c] = f2tf32(v);
        }
        __syncthreads();

        #pragma unroll
        for (int kk=0; kk<2; kk++){
            int kb = kk*8;
            uint32_t a[2][4];
            #pragma unroll
            for (int m=0;m<2;m++){
                int mr = wm*32 + m*16;
                a[m][0] = As[kb+tig  ][mr+gid  ];
                a[m][1] = As[kb+tig  ][mr+gid+8];
                a[m][2] = As[kb+tig+4][mr+gid  ];
                a[m][3] = As[kb+tig+4][mr+gid+8];
            }
            uint32_t b[4][2];
            #pragma unroll
            for (int n=0;n<4;n++){
                int nc = wn*32 + n*8;
                b[n][0] = Bs[kb+tig  ][nc+gid];
                b[n][1] = Bs[kb+tig+4][nc+gid];
            }
            #pragma unroll
            for (int m=0;m<2;m++)
                #pragma unroll
                for (int n=0;n<4;n++){
                    asm volatile(
                        "mma.sync.aligned.m16n8k8.row.col.f32.tf32.tf32.f32 "
                        "{%0,%1,%2,%3}, {%4,%5,%6,%7}, {%8,%9}, {%0,%1,%2,%3};"
                        : "+f"(acc[m][n][0]), "+f"(acc[m][n][1]),
                          "+f"(acc[m][n][2]), "+f"(acc[m][n][3])
                        : "r"(a[m][0]), "r"(a[m][1]), "r"(a[m][2]), "r"(a[m][3]),
                          "r"(b[n][0]), "r"(b[n][1]));
                }
        }
        __syncthreads();
    }
    // epilogue: c0 (g,2t) c1 (g,2t+1) c2 (g+8,2t) c3 (g+8,2t+1)
    #pragma unroll
    for (int m=0;m<2;m++){
        int row0 = bm + wm*32 + m*16 + gid;
        #pragma unroll
        for (int n=0;n<4;n++){
            int col = bn + wn*32 + n*8 + tig*2;
            if (col < N){
                C[(size_t)row0*N + col] = acc[m][n][0];
                C[(size_t)(row0+8)*N + col] = acc[m][n][2];
            }
            if (col+1 < N){
                C[(size_t)row0*N + col + 1] = acc[m][n][1];
                C[(size_t)(row0+8)*N + col + 1] = acc[m][n][3];
            }
        }
    }
}

// ---------------- epilogue: x_ssm = silu(proj[:, :384]) ----------------
__global__ void k_silu_ssm(const float* __restrict__ proj, float* __restrict__ xssm){
    int idx = blockIdx.x*blockDim.x + threadIdx.x;
    if (idx >= ROWS*EC) return;
    int row = idx / EC, e = idx % EC;
    float v = proj[(size_t)row*768 + e];
    xssm[idx] = siluf(v);
}

// ---------------- build combined weight [w_zx | w_bc] (800 cols) ----------------
__global__ void k_wcomb(const float* __restrict__ wzx, const float* __restrict__ wbc,
                        float* __restrict__ wc){
    int idx = blockIdx.x*blockDim.x + threadIdx.x;
    if (idx >= EC*ZXW) return;
    int kk = idx / ZXW, j = idx % ZXW;
    wc[idx] = (j < 768) ? wzx[kk*768 + j] : wbc[kk*32 + (j-768)];
}

// ---------------- fp32 GEMV for dt path: dtr[row][h] = xssm[row]·w_dt[:,h] ----------------
// warp per row; w_dt staged in smem. dt must stay fp32 (cumsum amplification).
__global__ __launch_bounds__(256) void k_dtgemv(const float* __restrict__ xssm,
                                                const float* __restrict__ w_dt,
                                                float* __restrict__ dtr){
    __shared__ float ws[EC*HHC];
    int tid = threadIdx.x;
    for (int i=tid; i<EC*HHC; i+=256) ws[i] = w_dt[i];
    __syncthreads();
    int warp = tid>>5, lane = tid&31;
    int row = blockIdx.x*8 + warp;
    float s[HHC];
    #pragma unroll
    for (int h=0;h<HHC;h++) s[h]=0.f;
    #pragma unroll
    for (int j=0;j<12;j++){
        int k = lane + j*32;
        float xv = xssm[(size_t)row*EC + k];
        #pragma unroll
        for (int h=0;h<HHC;h++) s[h] = fmaf(xv, ws[k*HHC+h], s[h]);
    }
    #pragma unroll
    for (int h=0;h<HHC;h++){
        #pragma unroll
        for (int off=16; off>=1; off>>=1) s[h] += __shfl_xor_sync(0xffffffffu, s[h], off);
    }
    if (lane < HHC) dtr[(size_t)row*HHC + lane] = s[lane];
    // note: lane h holds the fully reduced value only for s[h]; write per-lane:
}

// ---------------- dt = softplus(..+bias), r = exp(-dt*exp(A_log)), cumsum(dt) ----------------
__global__ void k_dtscan(const float* __restrict__ dtr, const float* __restrict__ dt_bias,
                         const float* __restrict__ A_log,
                         float* __restrict__ dtb, float* __restrict__ rb, float* __restrict__ cumb){
    int k = blockIdx.x / HHC, h = blockIdx.x % HHC;
    __shared__ float part[256];
    float expA = expf(A_log[h]);
    float bias = dt_bias[h];
    int tid = threadIdx.x;
    int tbase = tid*9;
    float loc[9]; float s = 0.f;
    #pragma unroll
    for (int i=0;i<9;i++){
        size_t row = (size_t)k*LSEQ + tbase + i;
        float v  = dtr[row*HHC + h] + bias;
        float dt = (v > 20.f) ? v : log1pf(expf(v));
        dtb[row*HHC+h] = dt;
        rb [row*HHC+h] = expf(-dt*expA);
        s += dt; loc[i] = s;
    }
    part[tid] = s; __syncthreads();
    for (int off=1; off<256; off<<=1){
        float add = (tid >= off) ? part[tid-off] : 0.f;
        __syncthreads();
        part[tid] += add;
        __syncthreads();
    }
    float offset = part[tid] - s;
    #pragma unroll
    for (int i=0;i<9;i++){
        size_t row = (size_t)k*LSEQ + tbase + i;
        cumb[row*HHC+h] = loc[i] + offset;
    }
}

// ---------------- rms(B/C) + rotary -> Bt, Ct ----------------
__global__ void k_rot(const float* __restrict__ zx, const float* __restrict__ b_bc,
                      const float* __restrict__ theta, const float* __restrict__ cumb,
                      float* __restrict__ Bt, float* __restrict__ Ct){
    int row = blockIdx.x*blockDim.x + threadIdx.x;
    if (row >= ROWS) return;
    const float* bc = zx + (size_t)row*ZXW + 768;
    float b[16], c[16];
    float sb = 0.f, sc = 0.f;
    #pragma unroll
    for (int i=0;i<16;i++){ b[i] = bc[i]    + b_bc[i];    sb += b[i]*b[i]; }
    #pragma unroll
    for (int i=0;i<16;i++){ c[i] = bc[16+i] + b_bc[16+i]; sc += c[i]*c[i]; }
    float rB = rsqrtf(sb*(1.f/16.f) + 1e-6f);
    float rC = rsqrtf(sc*(1.f/16.f) + 1e-6f);
    #pragma unroll
    for (int h=0; h<HHC; h++){
        float cd = cumb[(size_t)row*HHC + h];
        float* Bo = Bt + ((size_t)row*HHC + h)*16;
        float* Co = Ct + ((size_t)row*HHC + h)*16;
        #pragma unroll
        for (int i=0;i<8;i++){
            float ss, cc;
            sincosf(cd*theta[h*8+i], &ss, &cc);
            float v0 = b[2*i]*rB, v1 = b[2*i+1]*rB;
            Bo[2*i]   =  v0*cc + v1*ss;
            Bo[2*i+1] = -v0*ss + v1*cc;
            v0 = c[2*i]*rC; v1 = c[2*i+1]*rC;
            Co[2*i]   =  v0*cc + v1*ss;
            Co[2*i+1] = -v0*ss + v1*cc;
        }
    }
}

// ---------------- sequential selective scan ----------------
__global__ __launch_bounds__(256) void k_scan(const float* __restrict__ Bt, const float* __restrict__ Ct,
                                              const float* __restrict__ zx, const float* __restrict__ dtb,
                                              const float* __restrict__ rb, const float* __restrict__ Dsk,
                                              float* __restrict__ y){
    int kh = blockIdx.x; int k = kh/HHC, h = kh%HHC;
    int n = threadIdx.x & 15;
    int p = (blockIdx.y << 4) + (threadIdx.x >> 4);
    size_t rowB = ((size_t)k*LSEQ*HHC + h)*16 + n;
    size_t rowX = (size_t)k*LSEQ*ZXW + 384 + h*64 + p;
    size_t rowS = (size_t)k*LSEQ*HHC + h;
    float dsk = Dsk[h];
    float* yout = y + (size_t)k*LSEQ*EC + h*64 + p;
    float hs = 0.f, Bp = 0.f, xp = 0.f;
    float Bc = Bt[rowB], Cc = Ct[rowB], xc = zx[rowX], dtc = dtb[rowS], rc = rb[rowS];
    for (int t=0; t<LSEQ; ++t){
        float Bn2=0.f, Cn2=0.f, xn2=0.f, dtn2=0.f, rn2=0.f;
        if (t+1 < LSEQ){
            Bn2 = Bt[rowB+96]; Cn2 = Ct[rowB+96]; xn2 = zx[rowX+ZXW];
            dtn2 = dtb[rowS+HHC]; rn2 = rb[rowS+HHC];
        }
        float inp = 0.5f*dtc*(Bc*xc + rc*Bp*xp);
        hs = fmaf(rc, hs, inp);
        float v = Cc*hs;
        v += __shfl_xor_sync(0xffffffffu, v, 8);
        v += __shfl_xor_sync(0xffffffffu, v, 4);
        v += __shfl_xor_sync(0xffffffffu, v, 2);
        v += __shfl_xor_sync(0xffffffffu, v, 1);
        if (n == 0) yout[(size_t)t*EC] = v + dsk*xc;
        Bp = Bc; xp = xc;
        Bc = Bn2; Cc = Cn2; xc = xn2; dtc = dtn2; rc = rn2;
        rowB += 96; rowX += ZXW; rowS += HHC;
    }
}

// ---------------- g = rms(y * silu(z)) * rms_w  (warp per row) ----------------
__global__ void k_gate(const float* __restrict__ y, const float* __restrict__ zx,
                       const float* __restrict__ rms_w, float* __restrict__ g){
    int warp = (blockIdx.x*blockDim.x + threadIdx.x) >> 5;
    int lane = threadIdx.x & 31;
    if (warp >= ROWS) return;
    size_t ybase = (size_t)warp*EC;
    size_t zbase = (size_t)warp*ZXW;
    float v[12]; float s2 = 0.f;
    #pragma unroll
    for (int j=0;j<12;j++){
        int e = lane + j*32;
        float z = zx[zbase + e];
        float t = y[ybase + e] * siluf(z);
        v[j] = t; s2 += t*t;
    }
    #pragma unroll
    for (int off=16; off>=1; off>>=1) s2 += __shfl_xor_sync(0xffffffffu, s2, off);
    float rn = rsqrtf(s2*(1.f/384.f) + 1e-6f);
    #pragma unroll
    for (int j=0;j<12;j++){
        int e = lane + j*32;
        g[ybase + e] = v[j]*rn*rms_w[e];
    }
}

// ---------------- x_out = mamba_out * silu(x_gate) ----------------
__global__ void k_xout(const float* __restrict__ mo, const float* __restrict__ proj,
                       float* __restrict__ xout){
    int idx = blockIdx.x*blockDim.x + threadIdx.x;
    if (idx >= ROWS*EC) return;
    int row = idx / EC, e = idx % EC;
    float gv = proj[(size_t)row*768 + 384 + e];
    xout[idx] = mo[idx] * siluf(gv);
}

// ---------------- merge 4 directions -> mergedT[l][e] ----------------
__global__ void k_merge(const float* __restrict__ xout, float* __restrict__ mT){
    int idx = blockIdx.x*blockDim.x + threadIdx.x;
    if (idx >= LSEQ*EC) return;
    int l = idx / EC, e = idx % EC;
    int lt = (l%48)*48 + l/48;
    float v = xout[(size_t)l*EC + e]
            + xout[(size_t)(LSEQ + lt)*EC + e]
            + xout[(size_t)(2*LSEQ + 2303 - l)*EC + e]
            + xout[(size_t)(3*LSEQ + 2303 - lt)*EC + e];
    mT[idx] = v;
}

// ---------------- LayerNorm (over DIM per spatial) + residual ----------------
__global__ void k_ln(const float* __restrict__ pre, const float* __restrict__ x,
                     const float* __restrict__ ln_g, const float* __restrict__ ln_b,
                     const float* __restrict__ res_scale, float* __restrict__ out){
    int warp = (blockIdx.x*blockDim.x + threadIdx.x) >> 5;
    int lane = threadIdx.x & 31;
    if (warp >= LSEQ) return;
    int l = warp;
    float v[6]; float s = 0.f;
    #pragma unroll
    for (int j=0;j<6;j++){ v[j] = pre[(size_t)l*DIMC + lane + j*32]; s += v[j]; }
    #pragma unroll
    for (int off=16; off>=1; off>>=1) s += __shfl_xor_sync(0xffffffffu, s, off);
    float mu = s*(1.f/192.f);
    float q = 0.f;
    #pragma unroll
    for (int j=0;j<6;j++){ float d = v[j]-mu; q += d*d; }
    #pragma unroll
    for (int off=16; off>=1; off>>=1) q += __shfl_xor_sync(0xffffffffu, q, off);
    float inv = rsqrtf(q*(1.f/192.f) + 1e-5f);
    float rs = res_scale[0];
    #pragma unroll
    for (int j=0;j<6;j++){
        int d = lane + j*32;
        out[(size_t)d*LSEQ + l] = x[(size_t)d*LSEQ + l]
            + rs*((v[j]-mu)*inv*ln_g[d] + ln_b[d]);
    }
}

// ---------------- launch ----------------
extern "C" void kernel_launch(void* const* d_in, const int* in_sizes, int n_in,
                              void* d_out, int out_size){
    (void)in_sizes; (void)n_in; (void)out_size;
    const float* x        = (const float*)d_in[0];
    const float* w_in     = (const float*)d_in[1];
    const float* w_zx     = (const float*)d_in[2];
    const float* w_bc     = (const float*)d_in[3];
    const float* b_bc     = (const float*)d_in[4];
    const float* w_dt     = (const float*)d_in[5];
    const float* dt_bias  = (const float*)d_in[6];
    const float* A_log    = (const float*)d_in[7];
    const float* theta    = (const float*)d_in[8];
    const float* D_skip   = (const float*)d_in[9];
    const float* rms_w    = (const float*)d_in[10];
    const float* w_mout   = (const float*)d_in[11];
    const float* w_out    = (const float*)d_in[12];
    const float* ln_g     = (const float*)d_in[13];
    const float* ln_b     = (const float*)d_in[14];
    const float* resscale = (const float*)d_in[15];
    float* out = (float*)d_out;

    float *b_xseq, *b_proj, *b_xssm, *b_wcomb, *b_zx, *b_dtr, *b_dtb, *b_rb, *b_cum;
    float *b_Bt, *b_Ct, *b_y, *b_g, *b_mo, *b_xout, *b_mT, *b_pre;
    cudaGetSymbolAddress((void**)&b_xseq, g_xseq);
    cudaGetSymbolAddress((void**)&b_proj, g_proj);
    cudaGetSymbolAddress((void**)&b_xssm, g_xssm);
    cudaGetSymbolAddress((void**)&b_wcomb, g_wcomb);
    cudaGetSymbolAddress((void**)&b_zx,   g_zx);
    cudaGetSymbolAddress((void**)&b_dtr,  g_dtr);
    cudaGetSymbolAddress((void**)&b_dtb,  g_dtb);
    cudaGetSymbolAddress((void**)&b_rb,   g_rb);
    cudaGetSymbolAddress((void**)&b_cum,  g_cum);
    cudaGetSymbolAddress((void**)&b_Bt,   g_Bt);
    cudaGetSymbolAddress((void**)&b_Ct,   g_Ct);
    cudaGetSymbolAddress((void**)&b_y,    g_y);
    cudaGetSymbolAddress((void**)&b_g,    g_g);
    cudaGetSymbolAddress((void**)&b_mo,   g_mo);
    cudaGetSymbolAddress((void**)&b_xout, g_xout);
    cudaGetSymbolAddress((void**)&b_mT,   g_mT);
    cudaGetSymbolAddress((void**)&b_pre,  g_pre);

    // 0: direction sequences
    k_build<<<(ROWS*DIMC+255)/256, 256>>>(x, b_xseq);
    // 1: proj = x_seq @ w_in  (9216 x 768 x 192)  [tf32]
    k_gemm_tf32<<<dim3(768/64, ROWS/128), 256>>>(b_xseq, w_in, b_proj, ROWS, 768, DIMC);
    // 2: silu of ssm half
    k_silu_ssm<<<(ROWS*EC+255)/256, 256>>>(b_proj, b_xssm);
    // 3: combined weight + zx/bc GEMM (9216 x 800 x 384)  [tf32]
    k_wcomb<<<(EC*ZXW+255)/256, 256>>>(w_zx, w_bc, b_wcomb);
    k_gemm_tf32<<<dim3((ZXW+63)/64, ROWS/128), 256>>>(b_xssm, b_wcomb, b_zx, ROWS, ZXW, EC);
    // 3b: dt GEMV in fp32 (precision-critical path)
    k_dtgemv<<<ROWS/8, 256>>>(b_xssm, w_dt, b_dtr);
    // 4: dt / r / cumsum(dt)
    k_dtscan<<<KC*HHC, 256>>>(b_dtr, dt_bias, A_log, b_dtb, b_rb, b_cum);
    // 5: rms + rotary for B and C
    k_rot<<<(ROWS+127)/128, 128>>>(b_zx, b_bc, theta, b_cum, b_Bt, b_Ct);
    // 6: sequential scan -> y (+ D_skip * xh)
    k_scan<<<dim3(KC*HHC, 4), 256>>>(b_Bt, b_Ct, b_zx, b_dtb, b_rb, D_skip, b_y);
    // 7: gated rms norm
    k_gate<<<(ROWS*32+255)/256, 256>>>(b_y, b_zx, rms_w, b_g);
    // 8: mamba out GEMM (9216 x 384 x 384)  [tf32]
    k_gemm_tf32<<<dim3(EC/64, ROWS/128), 256>>>(b_g, w_mout, b_mo, ROWS, EC, EC);
    // 9: gate multiply
    k_xout<<<(ROWS*EC+255)/256, 256>>>(b_mo, b_proj, b_xout);
    // 10: merge 4 directions
    k_merge<<<(LSEQ*EC+255)/256, 256>>>(b_xout, b_mT);
    // 11: output projection GEMM (2304 x 192 x 384)  [tf32]
    k_gemm_tf32<<<dim3(DIMC/64, LSEQ/128), 256>>>(b_mT, w_out, b_pre, LSEQ, DIMC, EC);
    // 12: layernorm + residual -> d_out
    k_ln<<<(LSEQ*32+255)/256, 256>>>(b_pre, x, ln_g, ln_b, resscale, out);
}

// round 4
// speedup vs baseline: 2.3890x; 1.9324x over previous
#include <cuda_runtime.h>
#include <cstdint>
#include <math.h>

#define LSEQ 2304
#define DIMC 192
#define EC   384
#define NC   16
#define PC   64
#define HHC  6
#define KC   4
#define ROWS (KC*LSEQ)   /* 9216 */
#define ZXW  800         /* 768 (zx) + 32 (bc); dt handled separately in fp32 */

// ---------------- scratch (static device globals; no allocation) ----------------
static __device__ __align__(16) float g_xseq[ROWS*DIMC];      // tf32-rounded
static __device__ __align__(16) float g_proj[ROWS*768];       // fp32
static __device__ __align__(16) float g_xssmt[ROWS*EC];       // tf32-rounded silu(proj)
static __device__ __align__(16) float g_wcomb[EC*ZXW];        // tf32-rounded
static __device__ __align__(16) float g_winT[DIMC*768];       // tf32-rounded
static __device__ __align__(16) float g_wmoutT[EC*EC];        // tf32-rounded
static __device__ __align__(16) float g_woutT[EC*DIMC];       // tf32-rounded
static __device__ __align__(16) float g_zx[(size_t)ROWS*ZXW]; // fp32
static __device__ __align__(16) float g_dtr[ROWS*HHC];
static __device__ __align__(16) float g_dtb[ROWS*HHC];        // 0.5*dt
static __device__ __align__(16) float g_rb[ROWS*HHC];
static __device__ __align__(16) float g_cum[ROWS*HHC];
static __device__ __align__(16) float g_Bt[ROWS*HHC*NC];
static __device__ __align__(16) float g_Ct[ROWS*HHC*NC];
static __device__ __align__(16) float g_y[ROWS*EC];
static __device__ __align__(16) float g_g[ROWS*EC];           // tf32-rounded
static __device__ __align__(16) float g_mo[ROWS*EC];
static __device__ __align__(16) float g_mT[LSEQ*EC];          // tf32-rounded
static __device__ __align__(16) float g_pre[LSEQ*DIMC];

__device__ __forceinline__ float siluf(float v){ return v / (1.f + expf(-v)); }

__device__ __forceinline__ float f2tf32f(float f){
    uint32_t u; asm("cvt.rna.tf32.f32 %0, %1;" : "=r"(u) : "f"(f));
    return __uint_as_float(u);
}

#define CP16(dst,src) asm volatile("cp.async.cg.shared.global [%0],[%1],16;\n"::"r"(dst),"l"(src))
#define CP16Z(dst,src) asm volatile("cp.async.cg.shared.global [%0],[%1],16,0;\n"::"r"(dst),"l"(src))
#define CP4(dst,src)  asm volatile("cp.async.ca.shared.global [%0],[%1],4;\n"::"r"(dst),"l"(src))
#define CPCOMMIT()    asm volatile("cp.async.commit_group;\n")
#define CPWAIT1()     asm volatile("cp.async.wait_group 1;\n")

// ---------------- K0: build 4-direction sequence (smem-staged transpose, tf32 out) ----------------
// Reference does xs.reshape(Bn*K, L, DIM): flat reinterpretation of each (DIM,L)
// plane as (L,DIM). So xseq[k][d*LSEQ + l] = x[d][m_k(l)].
__global__ __launch_bounds__(256) void k_build(const float* __restrict__ x, float* __restrict__ xseq){
    __shared__ float sm[LSEQ + LSEQ/48];   // pad: idx + idx/48 -> conflict-free stride
    int d = blockIdx.x;          // 0..191
    int k = blockIdx.y;          // 0..3
    int tid = threadIdx.x;
    for (int i = tid; i < LSEQ; i += 256)
        sm[i + i/48] = x[d*LSEQ + i];
    __syncthreads();
    size_t obase = (size_t)k*(LSEQ*DIMC) + (size_t)d*LSEQ;
    for (int l = tid; l < LSEQ; l += 256){
        int m;
        if      (k==0) m = l;
        else if (k==1) m = (l%48)*48 + l/48;
        else if (k==2) m = 2303 - l;
        else { int lr = 2303-l; m = (lr%48)*48 + lr/48; }
        xseq[obase + l] = f2tf32f(sm[m + m/48]);
    }
}

// ---------------- generic tf32 convert ----------------
__global__ void k_cvt(const float* __restrict__ src, float* __restrict__ dst, int n){
    int i = blockIdx.x*blockDim.x + threadIdx.x;
    if (i < n) dst[i] = f2tf32f(src[i]);
}

// ---------------- tf32 tensor-core GEMM, cp.async double-buffered ----------------
// A,B hold tf32-rounded fp32 values (low mantissa bits zero). C fp32.
// M % 128 == 0, K % 16 == 0, N arbitrary (4-aligned). 256 threads, 8 warps 4x2,
// warp tile 32x32, mma m16n8k8.
__global__ __launch_bounds__(256) void k_gemm_tf32p(const float* __restrict__ A,
                                                    const float* __restrict__ B,
                                                    float* __restrict__ C,
                                                    int M, int N, int K){
    const int BM=128, BN=64, BK=16;
    __shared__ __align__(16) float As[2][BM][BK+4];   // stride 20: conflict-free frag loads
    __shared__ __align__(16) float Bs[2][BK][BN+8];   // stride 72: conflict-free frag loads
    int tid  = threadIdx.x;
    int warp = tid>>5, lane = tid&31;
    int wm = warp>>1, wn = warp&1;
    int gid = lane>>2, tig = lane&3;
    int bm = blockIdx.y*BM, bn = blockIdx.x*BN;

    float acc[2][4][4];
    #pragma unroll
    for (int m=0;m<2;m++)
        #pragma unroll
        for (int n=0;n<4;n++)
            #pragma unroll
            for (int i=0;i<4;i++) acc[m][n][i]=0.f;

    auto stage = [&](int buf, int k0){
        #pragma unroll
        for (int j=0;j<2;j++){
            int id = tid*2 + j;
            int r = id>>2, kc = id&3;
            uint32_t dst = (uint32_t)__cvta_generic_to_shared(&As[buf][r][kc*4]);
            const float* src = &A[(size_t)(bm+r)*K + k0 + kc*4];
            CP16(dst, src);
        }
        {
            int r = tid>>4, c = tid&15;
            uint32_t dst = (uint32_t)__cvta_generic_to_shared(&Bs[buf][r][c*4]);
            if (bn + c*4 + 4 <= N){
                const float* src = &B[(size_t)(k0+r)*N + bn + c*4];
                CP16(dst, src);
            } else {
                CP16Z(dst, B);
            }
        }
        CPCOMMIT();
    };

    int nk = K/BK;
    stage(0, 0);
    for (int kt=0; kt<nk; ++kt){
        int buf = kt&1;
        if (kt+1 < nk) stage(buf^1, (kt+1)*BK);
        else CPCOMMIT();
        CPWAIT1();
        __syncthreads();

        #pragma unroll
        for (int kk=0; kk<2; kk++){
            int kb = kk*8;
            uint32_t a[2][4];
            #pragma unroll
            for (int m=0;m<2;m++){
                int mr = wm*32 + m*16;
                a[m][0] = __float_as_uint(As[buf][mr+gid  ][kb+tig  ]);
                a[m][1] = __float_as_uint(As[buf][mr+gid+8][kb+tig  ]);
                a[m][2] = __float_as_uint(As[buf][mr+gid  ][kb+tig+4]);
                a[m][3] = __float_as_uint(As[buf][mr+gid+8][kb+tig+4]);
            }
            uint32_t b[4][2];
            #pragma unroll
            for (int n=0;n<4;n++){
                int nc = wn*32 + n*8;
                b[n][0] = __float_as_uint(Bs[buf][kb+tig  ][nc+gid]);
                b[n][1] = __float_as_uint(Bs[buf][kb+tig+4][nc+gid]);
            }
            #pragma unroll
            for (int m=0;m<2;m++)
                #pragma unroll
                for (int n=0;n<4;n++){
                    asm volatile(
                        "mma.sync.aligned.m16n8k8.row.col.f32.tf32.tf32.f32 "
                        "{%0,%1,%2,%3}, {%4,%5,%6,%7}, {%8,%9}, {%0,%1,%2,%3};"
                        : "+f"(acc[m][n][0]), "+f"(acc[m][n][1]),
                          "+f"(acc[m][n][2]), "+f"(acc[m][n][3])
                        : "r"(a[m][0]), "r"(a[m][1]), "r"(a[m][2]), "r"(a[m][3]),
                          "r"(b[n][0]), "r"(b[n][1]));
                }
        }
        __syncthreads();
    }
    #pragma unroll
    for (int m=0;m<2;m++){
        int row0 = bm + wm*32 + m*16 + gid;
        #pragma unroll
        for (int n=0;n<4;n++){
            int col = bn + wn*32 + n*8 + tig*2;
            if (col < N){
                C[(size_t)row0*N + col] = acc[m][n][0];
                C[(size_t)(row0+8)*N + col] = acc[m][n][2];
            }
            if (col+1 < N){
                C[(size_t)row0*N + col + 1] = acc[m][n][1];
                C[(size_t)(row0+8)*N + col + 1] = acc[m][n][3];
            }
        }
    }
}

// ---------------- x_ssm(tf32) = tf32(silu(proj[:, :384])) ----------------
__global__ void k_silu_t(const float* __restrict__ proj, float* __restrict__ xssmt){
    int idx = blockIdx.x*blockDim.x + threadIdx.x;
    if (idx >= ROWS*EC) return;
    int row = idx / EC, e = idx % EC;
    xssmt[idx] = f2tf32f(siluf(proj[(size_t)row*768 + e]));
}

// ---------------- build combined weight [w_zx | w_bc] (tf32) ----------------
__global__ void k_wcomb(const float* __restrict__ wzx, const float* __restrict__ wbc,
                        float* __restrict__ wc){
    int idx = blockIdx.x*blockDim.x + threadIdx.x;
    if (idx >= EC*ZXW) return;
    int kk = idx / ZXW, j = idx % ZXW;
    float v = (j < 768) ? wzx[kk*768 + j] : wbc[kk*32 + (j-768)];
    wc[idx] = f2tf32f(v);
}

// ---------------- fp32 GEMV for dt path (silu inline from proj) ----------------
__global__ __launch_bounds__(256) void k_dtgemv(const float* __restrict__ proj,
                                                const float* __restrict__ w_dt,
                                                float* __restrict__ dtr){
    __shared__ float ws[EC*HHC];
    int tid = threadIdx.x;
    for (int i=tid; i<EC*HHC; i+=256) ws[i] = w_dt[i];
    __syncthreads();
    int warp = tid>>5, lane = tid&31;
    int row = blockIdx.x*8 + warp;
    float s[HHC];
    #pragma unroll
    for (int h=0;h<HHC;h++) s[h]=0.f;
    #pragma unroll
    for (int j=0;j<12;j++){
        int k = lane + j*32;
        float xv = siluf(proj[(size_t)row*768 + k]);
        #pragma unroll
        for (int h=0;h<HHC;h++) s[h] = fmaf(xv, ws[k*HHC+h], s[h]);
    }
    #pragma unroll
    for (int h=0;h<HHC;h++){
        #pragma unroll
        for (int off=16; off>=1; off>>=1) s[h] += __shfl_xor_sync(0xffffffffu, s[h], off);
    }
    #pragma unroll
    for (int h=0;h<HHC;h++)
        if (lane == h) dtr[(size_t)row*HHC + h] = s[h];
}

// ---------------- dt path: softplus, r, cumsum; store HALF dt ----------------
__global__ void k_dtscan(const float* __restrict__ dtr, const float* __restrict__ dt_bias,
                         const float* __restrict__ A_log,
                         float* __restrict__ dtb, float* __restrict__ rb, float* __restrict__ cumb){
    int k = blockIdx.x / HHC, h = blockIdx.x % HHC;
    __shared__ float part[256];
    float expA = expf(A_log[h]);
    float bias = dt_bias[h];
    int tid = threadIdx.x;
    int tbase = tid*9;
    float loc[9]; float s = 0.f;
    #pragma unroll
    for (int i=0;i<9;i++){
        size_t row = (size_t)k*LSEQ + tbase + i;
        float v  = dtr[row*HHC + h] + bias;
        float dt = (v > 20.f) ? v : log1pf(expf(v));
        dtb[row*HHC+h] = 0.5f*dt;
        rb [row*HHC+h] = expf(-dt*expA);
        s += dt; loc[i] = s;
    }
    part[tid] = s; __syncthreads();
    for (int off=1; off<256; off<<=1){
        float add = (tid >= off) ? part[tid-off] : 0.f;
        __syncthreads();
        part[tid] += add;
        __syncthreads();
    }
    float offset = part[tid] - s;
    #pragma unroll
    for (int i=0;i<9;i++){
        size_t row = (size_t)k*LSEQ + tbase + i;
        cumb[row*HHC+h] = loc[i] + offset;
    }
}

// ---------------- rms(B/C) + rotary -> Bt, Ct ----------------
__global__ void k_rot(const float* __restrict__ zx, const float* __restrict__ b_bc,
                      const float* __restrict__ theta, const float* __restrict__ cumb,
                      float* __restrict__ Bt, float* __restrict__ Ct){
    int row = blockIdx.x*blockDim.x + threadIdx.x;
    if (row >= ROWS) return;
    const float* bc = zx + (size_t)row*ZXW + 768;
    float b[16], c[16];
    float sb = 0.f, sc = 0.f;
    #pragma unroll
    for (int i=0;i<16;i++){ b[i] = bc[i]    + b_bc[i];    sb += b[i]*b[i]; }
    #pragma unroll
    for (int i=0;i<16;i++){ c[i] = bc[16+i] + b_bc[16+i]; sc += c[i]*c[i]; }
    float rB = rsqrtf(sb*(1.f/16.f) + 1e-6f);
    float rC = rsqrtf(sc*(1.f/16.f) + 1e-6f);
    #pragma unroll
    for (int h=0; h<HHC; h++){
        float cd = cumb[(size_t)row*HHC + h];
        float* Bo = Bt + ((size_t)row*HHC + h)*16;
        float* Co = Ct + ((size_t)row*HHC + h)*16;
        #pragma unroll
        for (int i=0;i<8;i++){
            float ss, cc;
            sincosf(cd*theta[h*8+i], &ss, &cc);
            float v0 = b[2*i]*rB, v1 = b[2*i+1]*rB;
            Bo[2*i]   =  v0*cc + v1*ss;
            Bo[2*i+1] = -v0*ss + v1*cc;
            v0 = c[2*i]*rC; v1 = c[2*i+1]*rC;
            Co[2*i]   =  v0*cc + v1*ss;
            Co[2*i+1] = -v0*ss + v1*cc;
        }
    }
}

// ---------------- sequential selective scan, smem chunk staging ----------------
// block per (k,h) = 24 blocks, 256 threads: p = tid>>2 (64), ng = tid&3 (4 n each).
// cp.async double-buffered 32-step chunks; output staged in smem, flushed coalesced.
#define SCH 32
__global__ __launch_bounds__(256) void k_scan2(const float* __restrict__ Bt, const float* __restrict__ Ct,
                                               const float* __restrict__ zx, const float* __restrict__ dtb,
                                               const float* __restrict__ rb, const float* __restrict__ Dsk,
                                               float* __restrict__ y){
    __shared__ __align__(16) float Bs[2][SCH][16];
    __shared__ __align__(16) float Cs[2][SCH][16];
    __shared__ __align__(16) float Xs[2][SCH][64];
    __shared__ float Ds[2][SCH];
    __shared__ float Rs[2][SCH];
    __shared__ __align__(16) float Ys[SCH][64];

    int kh = blockIdx.x; int k = kh/HHC, h = kh%HHC;
    int tid = threadIdx.x;
    int p = tid>>2, ng = tid&3;
    size_t bBase = ((size_t)k*LSEQ*HHC + h)*16;
    size_t xBase = (size_t)k*LSEQ*ZXW + 384 + (size_t)h*64;
    size_t sBase = (size_t)k*LSEQ*HHC + h;
    float dsk = Dsk[h];
    float* ybase = y + (size_t)k*LSEQ*EC + h*64;

    auto stage = [&](int buf, int t0){
        // B or C: 128 16B-chunks each (32 t x 4 segs)
        {
            int id = tid & 127;
            int tl = id>>2, seg = id&3;
            size_t off = bBase + (size_t)(t0+tl)*96 + seg*4;
            if (tid < 128){
                uint32_t d = (uint32_t)__cvta_generic_to_shared(&Bs[buf][tl][seg*4]);
                CP16(d, &Bt[off]);
            } else {
                uint32_t d = (uint32_t)__cvta_generic_to_shared(&Cs[buf][tl][seg*4]);
                CP16(d, &Ct[off]);
            }
        }
        // X: 512 16B-chunks (32 t x 16 segs), 2 per thread
        #pragma unroll
        for (int j=0;j<2;j++){
            int i = tid + j*256;
            int tl = i>>4, c = i&15;
            uint32_t d = (uint32_t)__cvta_generic_to_shared(&Xs[buf][tl][c*4]);
            CP16(d, &zx[xBase + (size_t)(t0+tl)*ZXW + c*4]);
        }
        // D, R: 32 scalars each
        if (tid < SCH){
            uint32_t d = (uint32_t)__cvta_generic_to_shared(&Ds[buf][tid]);
            CP4(d, &dtb[sBase + (size_t)(t0+tid)*HHC]);
        } else if (tid < 2*SCH){
            int tl = tid - SCH;
            uint32_t d = (uint32_t)__cvta_generic_to_shared(&Rs[buf][tl]);
            CP4(d, &rb[sBase + (size_t)(t0+tl)*HHC]);
        }
        CPCOMMIT();
    };

    float hs0=0.f,hs1=0.f,hs2=0.f,hs3=0.f;
    float bx0=0.f,bx1=0.f,bx2=0.f,bx3=0.f;

    stage(0, 0);
    const int NCHUNK = LSEQ/SCH;   // 72
    for (int c=0; c<NCHUNK; ++c){
        int buf = c&1;
        if (c+1 < NCHUNK) stage(buf^1, (c+1)*SCH);
        else CPCOMMIT();
        CPWAIT1();
        __syncthreads();

        #pragma unroll 4
        for (int t=0; t<SCH; ++t){
            float4 Bv = *(const float4*)&Bs[buf][t][ng*4];
            float4 Cv = *(const float4*)&Cs[buf][t][ng*4];
            float xv = Xs[buf][t][p];
            float ad = Ds[buf][t];     // 0.5*dt
            float rv = Rs[buf][t];
            float G0 = Bv.x*xv, G1 = Bv.y*xv, G2 = Bv.z*xv, G3 = Bv.w*xv;
            float u0 = fmaf(rv,bx0,G0), u1 = fmaf(rv,bx1,G1);
            float u2 = fmaf(rv,bx2,G2), u3 = fmaf(rv,bx3,G3);
            hs0 = fmaf(rv,hs0,ad*u0); hs1 = fmaf(rv,hs1,ad*u1);
            hs2 = fmaf(rv,hs2,ad*u2); hs3 = fmaf(rv,hs3,ad*u3);
            bx0=G0; bx1=G1; bx2=G2; bx3=G3;
            float v = fmaf(Cv.x,hs0, fmaf(Cv.y,hs1, fmaf(Cv.z,hs2, Cv.w*hs3)));
            v += __shfl_xor_sync(0xffffffffu, v, 1);
            v += __shfl_xor_sync(0xffffffffu, v, 2);
            if (ng == 0) Ys[t][p] = fmaf(dsk, xv, v);
        }
        __syncthreads();
        // flush Ys (32 t x 64 p = 512 float4, 2 per thread)
        int t0 = c*SCH;
        #pragma unroll
        for (int j=0;j<2;j++){
            int i = tid + j*256;
            int tl = i>>4, cc = i&15;
            *(float4*)&ybase[(size_t)(t0+tl)*EC + cc*4] = *(const float4*)&Ys[tl][cc*4];
        }
    }
}

// ---------------- g = tf32(rms(y * silu(z)) * rms_w)  (warp per row) ----------------
__global__ void k_gate(const float* __restrict__ y, const float* __restrict__ zx,
                       const float* __restrict__ rms_w, float* __restrict__ g){
    int warp = (blockIdx.x*blockDim.x + threadIdx.x) >> 5;
    int lane = threadIdx.x & 31;
    if (warp >= ROWS) return;
    size_t ybase = (size_t)warp*EC;
    size_t zbase = (size_t)warp*ZXW;
    float v[12]; float s2 = 0.f;
    #pragma unroll
    for (int j=0;j<12;j++){
        int e = lane + j*32;
        float z = zx[zbase + e];
        float t = y[ybase + e] * siluf(z);
        v[j] = t; s2 += t*t;
    }
    #pragma unroll
    for (int off=16; off>=1; off>>=1) s2 += __shfl_xor_sync(0xffffffffu, s2, off);
    float rn = rsqrtf(s2*(1.f/384.f) + 1e-6f);
    #pragma unroll
    for (int j=0;j<12;j++){
        int e = lane + j*32;
        g[ybase + e] = f2tf32f(v[j]*rn*rms_w[e]);
    }
}

// ---------------- fused: x_out = mo * silu(gate); merge 4 dirs -> mT (tf32) ----------------
__global__ void k_xmerge(const float* __restrict__ mo, const float* __restrict__ proj,
                         float* __restrict__ mT){
    int idx = blockIdx.x*blockDim.x + threadIdx.x;
    if (idx >= LSEQ*EC) return;
    int l = idx / EC, e = idx % EC;
    int lt = (l%48)*48 + l/48;
    int r0 = l;
    int r1 = LSEQ + lt;
    int r2 = 2*LSEQ + 2303 - l;
    int r3 = 3*LSEQ + 2303 - lt;
    float v = mo[(size_t)r0*EC+e] * siluf(proj[(size_t)r0*768 + 384 + e])
            + mo[(size_t)r1*EC+e] * siluf(proj[(size_t)r1*768 + 384 + e])
            + mo[(size_t)r2*EC+e] * siluf(proj[(size_t)r2*768 + 384 + e])
            + mo[(size_t)r3*EC+e] * siluf(proj[(size_t)r3*768 + 384 + e]);
    mT[idx] = f2tf32f(v);
}

// ---------------- LayerNorm (over DIM per spatial) + residual ----------------
__global__ void k_ln(const float* __restrict__ pre, const float* __restrict__ x,
                     const float* __restrict__ ln_g, const float* __restrict__ ln_b,
                     const float* __restrict__ res_scale, float* __restrict__ out){
    int warp = (blockIdx.x*blockDim.x + threadIdx.x) >> 5;
    int lane = threadIdx.x & 31;
    if (warp >= LSEQ) return;
    int l = warp;
    float v[6]; float s = 0.f;
    #pragma unroll
    for (int j=0;j<6;j++){ v[j] = pre[(size_t)l*DIMC + lane + j*32]; s += v[j]; }
    #pragma unroll
    for (int off=16; off>=1; off>>=1) s += __shfl_xor_sync(0xffffffffu, s, off);
    float mu = s*(1.f/192.f);
    float q = 0.f;
    #pragma unroll
    for (int j=0;j<6;j++){ float d = v[j]-mu; q += d*d; }
    #pragma unroll
    for (int off=16; off>=1; off>>=1) q += __shfl_xor_sync(0xffffffffu, q, off);
    float inv = rsqrtf(q*(1.f/192.f) + 1e-5f);
    float rs = res_scale[0];
    #pragma unroll
    for (int j=0;j<6;j++){
        int d = lane + j*32;
        out[(size_t)d*LSEQ + l] = x[(size_t)d*LSEQ + l]
            + rs*((v[j]-mu)*inv*ln_g[d] + ln_b[d]);
    }
}

// ---------------- launch ----------------
extern "C" void kernel_launch(void* const* d_in, const int* in_sizes, int n_in,
                              void* d_out, int out_size){
    (void)in_sizes; (void)n_in; (void)out_size;
    const float* x        = (const float*)d_in[0];
    const float* w_in     = (const float*)d_in[1];
    const float* w_zx     = (const float*)d_in[2];
    const float* w_bc     = (const float*)d_in[3];
    const float* b_bc     = (const float*)d_in[4];
    const float* w_dt     = (const float*)d_in[5];
    const float* dt_bias  = (const float*)d_in[6];
    const float* A_log    = (const float*)d_in[7];
    const float* theta    = (const float*)d_in[8];
    const float* D_skip   = (const float*)d_in[9];
    const float* rms_w    = (const float*)d_in[10];
    const float* w_mout   = (const float*)d_in[11];
    const float* w_out    = (const float*)d_in[12];
    const float* ln_g     = (const float*)d_in[13];
    const float* ln_b     = (const float*)d_in[14];
    const float* resscale = (const float*)d_in[15];
    float* out = (float*)d_out;

    float *b_xseq,*b_proj,*b_xssmt,*b_wcomb,*b_winT,*b_wmoutT,*b_woutT,*b_zx;
    float *b_dtr,*b_dtb,*b_rb,*b_cum,*b_Bt,*b_Ct,*b_y,*b_g,*b_mo,*b_mT,*b_pre;
    cudaGetSymbolAddress((void**)&b_xseq,  g_xseq);
    cudaGetSymbolAddress((void**)&b_proj,  g_proj);
    cudaGetSymbolAddress((void**)&b_xssmt, g_xssmt);
    cudaGetSymbolAddress((void**)&b_wcomb, g_wcomb);
    cudaGetSymbolAddress((void**)&b_winT,  g_winT);
    cudaGetSymbolAddress((void**)&b_wmoutT,g_wmoutT);
    cudaGetSymbolAddress((void**)&b_woutT, g_woutT);
    cudaGetSymbolAddress((void**)&b_zx,    g_zx);
    cudaGetSymbolAddress((void**)&b_dtr,   g_dtr);
    cudaGetSymbolAddress((void**)&b_dtb,   g_dtb);
    cudaGetSymbolAddress((void**)&b_rb,    g_rb);
    cudaGetSymbolAddress((void**)&b_cum,   g_cum);
    cudaGetSymbolAddress((void**)&b_Bt,    g_Bt);
    cudaGetSymbolAddress((void**)&b_Ct,    g_Ct);
    cudaGetSymbolAddress((void**)&b_y,     g_y);
    cudaGetSymbolAddress((void**)&b_g,     g_g);
    cudaGetSymbolAddress((void**)&b_mo,    g_mo);
    cudaGetSymbolAddress((void**)&b_mT,    g_mT);
    cudaGetSymbolAddress((void**)&b_pre,   g_pre);

    // 0: direction sequences (tf32 out)
    k_build<<<dim3(DIMC, KC), 256>>>(x, b_xseq);
    // 0b: weight tf32 copies
    k_cvt<<<(DIMC*768+255)/256, 256>>>(w_in,   b_winT,  DIMC*768);
    k_cvt<<<(EC*EC+255)/256,   256>>>(w_mout, b_wmoutT, EC*EC);
    k_cvt<<<(EC*DIMC+255)/256, 256>>>(w_out,  b_woutT,  EC*DIMC);
    // 1: proj = x_seq @ w_in  (9216 x 768 x 192)
    k_gemm_tf32p<<<dim3(768/64, ROWS/128), 256>>>(b_xseq, b_winT, b_proj, ROWS, 768, DIMC);
    // 2: silu (tf32 out)
    k_silu_t<<<(ROWS*EC+255)/256, 256>>>(b_proj, b_xssmt);
    // 3: combined weight + zx/bc GEMM (9216 x 800 x 384)
    k_wcomb<<<(EC*ZXW+255)/256, 256>>>(w_zx, w_bc, b_wcomb);
    k_gemm_tf32p<<<dim3((ZXW+63)/64, ROWS/128), 256>>>(b_xssmt, b_wcomb, b_zx, ROWS, ZXW, EC);
    // 3b: dt GEMV in fp32 (precision-critical path; silu inline from proj)
    k_dtgemv<<<ROWS/8, 256>>>(b_proj, w_dt, b_dtr);
    // 4: dt / r / cumsum
    k_dtscan<<<KC*HHC, 256>>>(b_dtr, dt_bias, A_log, b_dtb, b_rb, b_cum);
    // 5: rms + rotary
    k_rot<<<(ROWS+127)/128, 128>>>(b_zx, b_bc, theta, b_cum, b_Bt, b_Ct);
    // 6: chunked selective scan
    k_scan2<<<KC*HHC, 256>>>(b_Bt, b_Ct, b_zx, b_dtb, b_rb, D_skip, b_y);
    // 7: gated rms norm (tf32 out)
    k_gate<<<(ROWS*32+255)/256, 256>>>(b_y, b_zx, rms_w, b_g);
    // 8: mamba out GEMM (9216 x 384 x 384)
    k_gemm_tf32p<<<dim3(EC/64, ROWS/128), 256>>>(b_g, b_wmoutT, b_mo, ROWS, EC, EC);
    // 9+10: fused gate-multiply + 4-direction merge (tf32 out)
    k_xmerge<<<(LSEQ*EC+255)/256, 256>>>(b_mo, b_proj, b_mT);
    // 11: output projection GEMM (2304 x 192 x 384)
    k_gemm_tf32p<<<dim3(DIMC/64, LSEQ/128), 256>>>(b_mT, b_woutT, b_pre, LSEQ, DIMC, EC);
    // 12: layernorm + residual -> d_out
    k_ln<<<(LSEQ*32+255)/256, 256>>>(b_pre, x, ln_g, ln_b, resscale, out);
}

// round 5
// speedup vs baseline: 3.5605x; 1.4904x over previous
#include <cuda_runtime.h>
#include <cstdint>
#include <math.h>

#define LSEQ 2304
#define DIMC 192
#define EC   384
#define NC   16
#define PC   64
#define HHC  6
#define KC   4
#define ROWS (KC*LSEQ)   /* 9216 */
#define ZXW  800         /* 768 (zx) + 32 (bc); dt handled separately in fp32 */
#define NSEG 8
#define TSEG (LSEQ/NSEG) /* 288 */

// ---------------- scratch (static device globals; no allocation) ----------------
static __device__ __align__(16) float g_xseq[ROWS*DIMC];      // tf32-rounded
static __device__ __align__(16) float g_proj[ROWS*768];       // fp32
static __device__ __align__(16) float g_xssmt[ROWS*EC];       // tf32-rounded silu(proj)
static __device__ __align__(16) float g_wcomb[EC*ZXW];        // tf32-rounded
static __device__ __align__(16) float g_winT[DIMC*768];       // tf32-rounded
static __device__ __align__(16) float g_wmoutT[EC*EC];        // tf32-rounded
static __device__ __align__(16) float g_woutT[EC*DIMC];       // tf32-rounded
static __device__ __align__(16) float g_zx[(size_t)ROWS*ZXW]; // fp32
static __device__ __align__(16) float g_dtr[ROWS*HHC];
static __device__ __align__(16) float g_dtb[ROWS*HHC];        // 0.5*dt
static __device__ __align__(16) float g_rb[ROWS*HHC];
static __device__ __align__(16) float g_cum[ROWS*HHC];
static __device__ __align__(16) float g_Bt[ROWS*HHC*NC];
static __device__ __align__(16) float g_Ct[ROWS*HHC*NC];
static __device__ __align__(16) float g_y[ROWS*EC];
static __device__ __align__(16) float g_g[ROWS*EC];           // tf32-rounded
static __device__ __align__(16) float g_mo[ROWS*EC];
static __device__ __align__(16) float g_mT[LSEQ*EC];          // tf32-rounded
static __device__ __align__(16) float g_pre[LSEQ*DIMC];
static __device__ __align__(16) float g_rc[KC*HHC*LSEQ];      // per-(k,h) segment-local cum decay
static __device__ __align__(16) float g_hend[KC*HHC*NSEG*PC*NC]; // local end states
static __device__ __align__(16) float g_hin[KC*HHC*NSEG*PC*NC];  // segment input states

__device__ __forceinline__ float siluf(float v){ return v / (1.f + expf(-v)); }

__device__ __forceinline__ float f2tf32f(float f){
    uint32_t u; asm("cvt.rna.tf32.f32 %0, %1;" : "=r"(u) : "f"(f));
    return __uint_as_float(u);
}

#define CP16(dst,src) asm volatile("cp.async.cg.shared.global [%0],[%1],16;\n"::"r"(dst),"l"(src))
#define CP16Z(dst,src) asm volatile("cp.async.cg.shared.global [%0],[%1],16,0;\n"::"r"(dst),"l"(src))
#define CP4(dst,src)  asm volatile("cp.async.ca.shared.global [%0],[%1],4;\n"::"r"(dst),"l"(src))
#define CPCOMMIT()    asm volatile("cp.async.commit_group;\n")
#define CPWAIT1()     asm volatile("cp.async.wait_group 1;\n")

// ---------------- K0: build 4-direction sequence (smem-staged, tf32 out) ----------------
__global__ __launch_bounds__(256) void k_build(const float* __restrict__ x, float* __restrict__ xseq){
    __shared__ float sm[LSEQ + LSEQ/48];
    int d = blockIdx.x;
    int k = blockIdx.y;
    int tid = threadIdx.x;
    for (int i = tid; i < LSEQ; i += 256)
        sm[i + i/48] = x[d*LSEQ + i];
    __syncthreads();
    size_t obase = (size_t)k*(LSEQ*DIMC) + (size_t)d*LSEQ;
    for (int l = tid; l < LSEQ; l += 256){
        int m;
        if      (k==0) m = l;
        else if (k==1) m = (l%48)*48 + l/48;
        else if (k==2) m = 2303 - l;
        else { int lr = 2303-l; m = (lr%48)*48 + lr/48; }
        xseq[obase + l] = f2tf32f(sm[m + m/48]);
    }
}

// ---------------- fused weight prep: tf32 copies of all weights ----------------
#define WP1 (DIMC*768)
#define WP2 (WP1 + EC*EC)
#define WP3 (WP2 + EC*DIMC)
#define WP4 (WP3 + EC*ZXW)
__global__ void k_wprep(const float* __restrict__ w_in, const float* __restrict__ w_mout,
                        const float* __restrict__ w_out, const float* __restrict__ wzx,
                        const float* __restrict__ wbc,
                        float* __restrict__ winT, float* __restrict__ wmoutT,
                        float* __restrict__ woutT, float* __restrict__ wcomb){
    int idx = blockIdx.x*blockDim.x + threadIdx.x;
    if (idx >= WP4) return;
    if (idx < WP1){ winT[idx] = f2tf32f(w_in[idx]); return; }
    if (idx < WP2){ int i = idx-WP1; wmoutT[i] = f2tf32f(w_mout[i]); return; }
    if (idx < WP3){ int i = idx-WP2; woutT[i] = f2tf32f(w_out[i]); return; }
    int i = idx-WP3;
    int kk = i / ZXW, j = i % ZXW;
    float v = (j < 768) ? wzx[kk*768 + j] : wbc[kk*32 + (j-768)];
    wcomb[i] = f2tf32f(v);
}

// ---------------- tf32 tensor-core GEMM, cp.async double-buffered ----------------
__global__ __launch_bounds__(256) void k_gemm_tf32p(const float* __restrict__ A,
                                                    const float* __restrict__ B,
                                                    float* __restrict__ C,
                                                    int M, int N, int K){
    const int BM=128, BN=64, BK=16;
    __shared__ __align__(16) float As[2][BM][BK+4];
    __shared__ __align__(16) float Bs[2][BK][BN+8];
    int tid  = threadIdx.x;
    int warp = tid>>5, lane = tid&31;
    int wm = warp>>1, wn = warp&1;
    int gid = lane>>2, tig = lane&3;
    int bm = blockIdx.y*BM, bn = blockIdx.x*BN;

    float acc[2][4][4];
    #pragma unroll
    for (int m=0;m<2;m++)
        #pragma unroll
        for (int n=0;n<4;n++)
            #pragma unroll
            for (int i=0;i<4;i++) acc[m][n][i]=0.f;

    auto stage = [&](int buf, int k0){
        #pragma unroll
        for (int j=0;j<2;j++){
            int id = tid*2 + j;
            int r = id>>2, kc = id&3;
            uint32_t dst = (uint32_t)__cvta_generic_to_shared(&As[buf][r][kc*4]);
            const float* src = &A[(size_t)(bm+r)*K + k0 + kc*4];
            CP16(dst, src);
        }
        {
            int r = tid>>4, c = tid&15;
            uint32_t dst = (uint32_t)__cvta_generic_to_shared(&Bs[buf][r][c*4]);
            if (bn + c*4 + 4 <= N){
                const float* src = &B[(size_t)(k0+r)*N + bn + c*4];
                CP16(dst, src);
            } else {
                CP16Z(dst, B);
            }
        }
        CPCOMMIT();
    };

    int nk = K/BK;
    stage(0, 0);
    for (int kt=0; kt<nk; ++kt){
        int buf = kt&1;
        if (kt+1 < nk) stage(buf^1, (kt+1)*BK);
        else CPCOMMIT();
        CPWAIT1();
        __syncthreads();

        #pragma unroll
        for (int kk=0; kk<2; kk++){
            int kb = kk*8;
            uint32_t a[2][4];
            #pragma unroll
            for (int m=0;m<2;m++){
                int mr = wm*32 + m*16;
                a[m][0] = __float_as_uint(As[buf][mr+gid  ][kb+tig  ]);
                a[m][1] = __float_as_uint(As[buf][mr+gid+8][kb+tig  ]);
                a[m][2] = __float_as_uint(As[buf][mr+gid  ][kb+tig+4]);
                a[m][3] = __float_as_uint(As[buf][mr+gid+8][kb+tig+4]);
            }
            uint32_t b[4][2];
            #pragma unroll
            for (int n=0;n<4;n++){
                int nc = wn*32 + n*8;
                b[n][0] = __float_as_uint(Bs[buf][kb+tig  ][nc+gid]);
                b[n][1] = __float_as_uint(Bs[buf][kb+tig+4][nc+gid]);
            }
            #pragma unroll
            for (int m=0;m<2;m++)
                #pragma unroll
                for (int n=0;n<4;n++){
                    asm volatile(
                        "mma.sync.aligned.m16n8k8.row.col.f32.tf32.tf32.f32 "
                        "{%0,%1,%2,%3}, {%4,%5,%6,%7}, {%8,%9}, {%0,%1,%2,%3};"
                        : "+f"(acc[m][n][0]), "+f"(acc[m][n][1]),
                          "+f"(acc[m][n][2]), "+f"(acc[m][n][3])
                        : "r"(a[m][0]), "r"(a[m][1]), "r"(a[m][2]), "r"(a[m][3]),
                          "r"(b[n][0]), "r"(b[n][1]));
                }
        }
        __syncthreads();
    }
    #pragma unroll
    for (int m=0;m<2;m++){
        int row0 = bm + wm*32 + m*16 + gid;
        #pragma unroll
        for (int n=0;n<4;n++){
            int col = bn + wn*32 + n*8 + tig*2;
            if (col < N){
                C[(size_t)row0*N + col] = acc[m][n][0];
                C[(size_t)(row0+8)*N + col] = acc[m][n][2];
            }
            if (col+1 < N){
                C[(size_t)row0*N + col + 1] = acc[m][n][1];
                C[(size_t)(row0+8)*N + col + 1] = acc[m][n][3];
            }
        }
    }
}

// ---------------- fused: xssmt = tf32(silu(proj)), dtr = silu(proj)·w_dt (fp32) ----------------
// warp per row; 8 warps/block. Single pass over proj[:, :384].
__global__ __launch_bounds__(256) void k_silu_dt(const float* __restrict__ proj,
                                                 const float* __restrict__ w_dt,
                                                 float* __restrict__ xssmt,
                                                 float* __restrict__ dtr){
    __shared__ float ws[EC*HHC];
    int tid = threadIdx.x;
    for (int i=tid; i<EC*HHC; i+=256) ws[i] = w_dt[i];
    __syncthreads();
    int warp = tid>>5, lane = tid&31;
    int row = blockIdx.x*8 + warp;
    float s[HHC];
    #pragma unroll
    for (int h=0;h<HHC;h++) s[h]=0.f;
    #pragma unroll
    for (int j=0;j<12;j++){
        int e = lane + j*32;
        float xv = siluf(proj[(size_t)row*768 + e]);
        xssmt[(size_t)row*EC + e] = f2tf32f(xv);
        #pragma unroll
        for (int h=0;h<HHC;h++) s[h] = fmaf(xv, ws[e*HHC+h], s[h]);
    }
    #pragma unroll
    for (int h=0;h<HHC;h++){
        #pragma unroll
        for (int off=16; off>=1; off>>=1) s[h] += __shfl_xor_sync(0xffffffffu, s[h], off);
    }
    #pragma unroll
    for (int h=0;h<HHC;h++)
        if (lane == h) dtr[(size_t)row*HHC + h] = s[h];
}

// ---------------- dt path: softplus, r, cumsum; store HALF dt ----------------
__global__ void k_dtscan(const float* __restrict__ dtr, const float* __restrict__ dt_bias,
                         const float* __restrict__ A_log,
                         float* __restrict__ dtb, float* __restrict__ rb, float* __restrict__ cumb){
    int k = blockIdx.x / HHC, h = blockIdx.x % HHC;
    __shared__ float part[256];
    float expA = expf(A_log[h]);
    float bias = dt_bias[h];
    int tid = threadIdx.x;
    int tbase = tid*9;
    float loc[9]; float s = 0.f;
    #pragma unroll
    for (int i=0;i<9;i++){
        size_t row = (size_t)k*LSEQ + tbase + i;
        float v  = dtr[row*HHC + h] + bias;
        float dt = (v > 20.f) ? v : log1pf(expf(v));
        dtb[row*HHC+h] = 0.5f*dt;
        rb [row*HHC+h] = expf(-dt*expA);
        s += dt; loc[i] = s;
    }
    part[tid] = s; __syncthreads();
    for (int off=1; off<256; off<<=1){
        float add = (tid >= off) ? part[tid-off] : 0.f;
        __syncthreads();
        part[tid] += add;
        __syncthreads();
    }
    float offset = part[tid] - s;
    #pragma unroll
    for (int i=0;i<9;i++){
        size_t row = (size_t)k*LSEQ + tbase + i;
        cumb[row*HHC+h] = loc[i] + offset;
    }
}

// ---------------- rms(B/C) + rotary -> Bt, Ct ----------------
__global__ void k_rot(const float* __restrict__ zx, const float* __restrict__ b_bc,
                      const float* __restrict__ theta, const float* __restrict__ cumb,
                      float* __restrict__ Bt, float* __restrict__ Ct){
    int row = blockIdx.x*blockDim.x + threadIdx.x;
    if (row >= ROWS) return;
    const float* bc = zx + (size_t)row*ZXW + 768;
    float b[16], c[16];
    float sb = 0.f, sc = 0.f;
    #pragma unroll
    for (int i=0;i<16;i++){ b[i] = bc[i]    + b_bc[i];    sb += b[i]*b[i]; }
    #pragma unroll
    for (int i=0;i<16;i++){ c[i] = bc[16+i] + b_bc[16+i]; sc += c[i]*c[i]; }
    float rB = rsqrtf(sb*(1.f/16.f) + 1e-6f);
    float rC = rsqrtf(sc*(1.f/16.f) + 1e-6f);
    #pragma unroll
    for (int h=0; h<HHC; h++){
        float cd = cumb[(size_t)row*HHC + h];
        float* Bo = Bt + ((size_t)row*HHC + h)*16;
        float* Co = Ct + ((size_t)row*HHC + h)*16;
        #pragma unroll
        for (int i=0;i<8;i++){
            float ss, cc;
            sincosf(cd*theta[h*8+i], &ss, &cc);
            float v0 = b[2*i]*rB, v1 = b[2*i+1]*rB;
            Bo[2*i]   =  v0*cc + v1*ss;
            Bo[2*i+1] = -v0*ss + v1*cc;
            v0 = c[2*i]*rC; v1 = c[2*i+1]*rC;
            Co[2*i]   =  v0*cc + v1*ss;
            Co[2*i+1] = -v0*ss + v1*cc;
        }
    }
}

// ---------------- scan phase A: per-segment local scan (h_in = 0) ----------------
// grid (24, NSEG); 256 thr: p = tid>>2, ng = tid&3 (4 states each).
// Emits y_loc, cumulative decay rc[t] (segment-local), and local end state.
#define SCH 32
__global__ __launch_bounds__(256) void k_scanA(const float* __restrict__ Bt, const float* __restrict__ Ct,
                                               const float* __restrict__ zx, const float* __restrict__ dtb,
                                               const float* __restrict__ rb, const float* __restrict__ Dsk,
                                               float* __restrict__ y, float* __restrict__ rc,
                                               float* __restrict__ hend){
    __shared__ __align__(16) float Bs[2][SCH][16];
    __shared__ __align__(16) float Cs[2][SCH][16];
    __shared__ __align__(16) float Xs[2][SCH][64];
    __shared__ float Ds[2][SCH];
    __shared__ float Rs[2][SCH];
    __shared__ __align__(16) float Ys[SCH][64];
    __shared__ float Rys[SCH];

    int kh = blockIdx.x; int k = kh/HHC, h = kh%HHC;
    int seg = blockIdx.y;
    int tseg0 = seg*TSEG;
    int tid = threadIdx.x;
    int p = tid>>2, ng = tid&3;
    size_t bBase = ((size_t)k*LSEQ*HHC + h)*16;
    size_t xBase = (size_t)k*LSEQ*ZXW + 384 + (size_t)h*64;
    size_t sBase = (size_t)k*LSEQ*HHC + h;
    float dsk = Dsk[h];
    float* ybase = y + (size_t)k*LSEQ*EC + h*64;
    size_t rcBase = (size_t)kh*LSEQ;

    auto stage = [&](int buf, int t0){
        {
            int id = tid & 127;
            int tl = id>>2, sg = id&3;
            size_t off = bBase + (size_t)(t0+tl)*96 + sg*4;
            if (tid < 128){
                uint32_t d = (uint32_t)__cvta_generic_to_shared(&Bs[buf][tl][sg*4]);
                CP16(d, &Bt[off]);
            } else {
                uint32_t d = (uint32_t)__cvta_generic_to_shared(&Cs[buf][tl][sg*4]);
                CP16(d, &Ct[off]);
            }
        }
        #pragma unroll
        for (int j=0;j<2;j++){
            int i = tid + j*256;
            int tl = i>>4, c = i&15;
            uint32_t d = (uint32_t)__cvta_generic_to_shared(&Xs[buf][tl][c*4]);
            CP16(d, &zx[xBase + (size_t)(t0+tl)*ZXW + c*4]);
        }
        if (tid < SCH){
            uint32_t d = (uint32_t)__cvta_generic_to_shared(&Ds[buf][tid]);
            CP4(d, &dtb[sBase + (size_t)(t0+tid)*HHC]);
        } else if (tid < 2*SCH){
            int tl = tid - SCH;
            uint32_t d = (uint32_t)__cvta_generic_to_shared(&Rs[buf][tl]);
            CP4(d, &rb[sBase + (size_t)(t0+tl)*HHC]);
        }
        CPCOMMIT();
    };

    float hs0=0.f,hs1=0.f,hs2=0.f,hs3=0.f;
    float bx0=0.f,bx1=0.f,bx2=0.f,bx3=0.f;
    // cross-segment u_prev: u_{t0-1} = B_{t0-1} x_{t0-1}
    if (seg > 0){
        int tp = tseg0 - 1;
        float4 Bp = *(const float4*)&Bt[bBase + (size_t)tp*96 + ng*4];
        float xp = zx[xBase + (size_t)tp*ZXW + p];
        bx0 = Bp.x*xp; bx1 = Bp.y*xp; bx2 = Bp.z*xp; bx3 = Bp.w*xp;
    }
    float rp = 1.f;

    stage(0, tseg0);
    const int NCHUNK = TSEG/SCH;   // 9
    for (int c=0; c<NCHUNK; ++c){
        int buf = c&1;
        if (c+1 < NCHUNK) stage(buf^1, tseg0 + (c+1)*SCH);
        else CPCOMMIT();
        CPWAIT1();
        __syncthreads();

        #pragma unroll 4
        for (int t=0; t<SCH; ++t){
            float4 Bv = *(const float4*)&Bs[buf][t][ng*4];
            float4 Cv = *(const float4*)&Cs[buf][t][ng*4];
            float xv = Xs[buf][t][p];
            float ad = Ds[buf][t];
            float rv = Rs[buf][t];
            float G0 = Bv.x*xv, G1 = Bv.y*xv, G2 = Bv.z*xv, G3 = Bv.w*xv;
            float u0 = fmaf(rv,bx0,G0), u1 = fmaf(rv,bx1,G1);
            float u2 = fmaf(rv,bx2,G2), u3 = fmaf(rv,bx3,G3);
            hs0 = fmaf(rv,hs0,ad*u0); hs1 = fmaf(rv,hs1,ad*u1);
            hs2 = fmaf(rv,hs2,ad*u2); hs3 = fmaf(rv,hs3,ad*u3);
            bx0=G0; bx1=G1; bx2=G2; bx3=G3;
            rp *= rv;
            float v = fmaf(Cv.x,hs0, fmaf(Cv.y,hs1, fmaf(Cv.z,hs2, Cv.w*hs3)));
            v += __shfl_xor_sync(0xffffffffu, v, 1);
            v += __shfl_xor_sync(0xffffffffu, v, 2);
            if (ng == 0) Ys[t][p] = fmaf(dsk, xv, v);
            if (tid == 0) Rys[t] = rp;
        }
        __syncthreads();
        int t0 = tseg0 + c*SCH;
        #pragma unroll
        for (int j=0;j<2;j++){
            int i = tid + j*256;
            int tl = i>>4, cc = i&15;
            *(float4*)&ybase[(size_t)(t0+tl)*EC + cc*4] = *(const float4*)&Ys[tl][cc*4];
        }
        if (tid < SCH) rc[rcBase + t0 + tid] = Rys[tid];
    }
    // store local end state
    float4 he = make_float4(hs0,hs1,hs2,hs3);
    *(float4*)&hend[(((size_t)kh*NSEG + seg)*PC + p)*NC + ng*4] = he;
}

// ---------------- scan phase B: sequential combine of segment boundary states ----------------
__global__ __launch_bounds__(256) void k_scanB(const float* __restrict__ hend,
                                               const float* __restrict__ rc,
                                               float* __restrict__ hin){
    int kh = blockIdx.x;
    int tid = threadIdx.x;
    int p = tid>>2, ng = tid&3;
    float4 hi = make_float4(0.f,0.f,0.f,0.f);
    #pragma unroll
    for (int s=0; s<NSEG; ++s){
        size_t idx = (((size_t)kh*NSEG + s)*PC + p)*NC + ng*4;
        *(float4*)&hin[idx] = hi;
        float4 he = *(const float4*)&hend[idx];
        float Rseg = rc[(size_t)kh*LSEQ + s*TSEG + TSEG-1];
        hi.x = fmaf(Rseg, hi.x, he.x);
        hi.y = fmaf(Rseg, hi.y, he.y);
        hi.z = fmaf(Rseg, hi.z, he.z);
        hi.w = fmaf(Rseg, hi.w, he.w);
    }
}

// ---------------- scan phase C: fixup y += R(t) * (C_t · h_in) ----------------
// grid (24, NSEG); 256 thr: p = tid&63, tq = tid>>6.
__global__ __launch_bounds__(256) void k_scanC(const float* __restrict__ Ct,
                                               const float* __restrict__ rc,
                                               const float* __restrict__ hin,
                                               float* __restrict__ y){
    int seg = blockIdx.y;
    if (seg == 0) return;   // h_in = 0
    __shared__ float Hs[PC][NC+1];
    __shared__ float Cs[SCH][NC+1];
    __shared__ float Rsh[SCH];
    int kh = blockIdx.x; int k = kh/HHC, h = kh%HHC;
    int tid = threadIdx.x;
    int p = tid&63, tq = tid>>6;
    size_t hBase = ((size_t)kh*NSEG + seg)*PC*NC;
    for (int i=tid; i<PC*NC; i+=256) Hs[i>>4][i&15] = hin[hBase + i];
    __syncthreads();
    float hn[NC];
    #pragma unroll
    for (int i=0;i<NC;i++) hn[i] = Hs[p][i];

    size_t bBase = ((size_t)k*LSEQ*HHC + h)*16;
    size_t rcBase = (size_t)kh*LSEQ;
    float* ybase = y + (size_t)k*LSEQ*EC + h*64;
    int tseg0 = seg*TSEG;

    for (int c=0; c<TSEG/SCH; ++c){
        int t0 = tseg0 + c*SCH;
        for (int i=tid; i<SCH*NC; i+=256){
            int tl = i>>4, nn = i&15;
            Cs[tl][nn] = Ct[bBase + (size_t)(t0+tl)*96 + nn];
        }
        if (tid < SCH) Rsh[tid] = rc[rcBase + t0 + tid];
        __syncthreads();
        if (Rsh[0] == 0.f) break;   // monotone decay: all later corrections are zero
        #pragma unroll
        for (int jt=0; jt<SCH/4; ++jt){
            int tl = tq + jt*4;
            float R = Rsh[tl];
            if (R != 0.f){
                float corr = 0.f;
                #pragma unroll
                for (int i=0;i<NC;i++) corr = fmaf(Cs[tl][i], hn[i], corr);
                ybase[(size_t)(t0+tl)*EC + p] += R*corr;
            }
        }
        __syncthreads();
    }
}

// ---------------- g = tf32(rms(y * silu(z)) * rms_w)  (warp per row) ----------------
__global__ void k_gate(const float* __restrict__ y, const float* __restrict__ zx,
                       const float* __restrict__ rms_w, float* __restrict__ g){
    int warp = (blockIdx.x*blockDim.x + threadIdx.x) >> 5;
    int lane = threadIdx.x & 31;
    if (warp >= ROWS) return;
    size_t ybase = (size_t)warp*EC;
    size_t zbase = (size_t)warp*ZXW;
    float v[12]; float s2 = 0.f;
    #pragma unroll
    for (int j=0;j<12;j++){
        int e = lane + j*32;
        float z = zx[zbase + e];
        float t = y[ybase + e] * siluf(z);
        v[j] = t; s2 += t*t;
    }
    #pragma unroll
    for (int off=16; off>=1; off>>=1) s2 += __shfl_xor_sync(0xffffffffu, s2, off);
    float rn = rsqrtf(s2*(1.f/384.f) + 1e-6f);
    #pragma unroll
    for (int j=0;j<12;j++){
        int e = lane + j*32;
        g[ybase + e] = f2tf32f(v[j]*rn*rms_w[e]);
    }
}

// ---------------- fused: x_out = mo * silu(gate); merge 4 dirs -> mT (tf32) ----------------
__global__ void k_xmerge(const float* __restrict__ mo, const float* __restrict__ proj,
                         float* __restrict__ mT){
    int idx = blockIdx.x*blockDim.x + threadIdx.x;
    if (idx >= LSEQ*EC) return;
    int l = idx / EC, e = idx % EC;
    int lt = (l%48)*48 + l/48;
    int r0 = l;
    int r1 = LSEQ + lt;
    int r2 = 2*LSEQ + 2303 - l;
    int r3 = 3*LSEQ + 2303 - lt;
    float v = mo[(size_t)r0*EC+e] * siluf(proj[(size_t)r0*768 + 384 + e])
            + mo[(size_t)r1*EC+e] * siluf(proj[(size_t)r1*768 + 384 + e])
            + mo[(size_t)r2*EC+e] * siluf(proj[(size_t)r2*768 + 384 + e])
            + mo[(size_t)r3*EC+e] * siluf(proj[(size_t)r3*768 + 384 + e]);
    mT[idx] = f2tf32f(v);
}

// ---------------- LayerNorm + residual ----------------
__global__ void k_ln(const float* __restrict__ pre, const float* __restrict__ x,
                     const float* __restrict__ ln_g, const float* __restrict__ ln_b,
                     const float* __restrict__ res_scale, float* __restrict__ out){
    int warp = (blockIdx.x*blockDim.x + threadIdx.x) >> 5;
    int lane = threadIdx.x & 31;
    if (warp >= LSEQ) return;
    int l = warp;
    float v[6]; float s = 0.f;
    #pragma unroll
    for (int j=0;j<6;j++){ v[j] = pre[(size_t)l*DIMC + lane + j*32]; s += v[j]; }
    #pragma unroll
    for (int off=16; off>=1; off>>=1) s += __shfl_xor_sync(0xffffffffu, s, off);
    float mu = s*(1.f/192.f);
    float q = 0.f;
    #pragma unroll
    for (int j=0;j<6;j++){ float d = v[j]-mu; q += d*d; }
    #pragma unroll
    for (int off=16; off>=1; off>>=1) q += __shfl_xor_sync(0xffffffffu, q, off);
    float inv = rsqrtf(q*(1.f/192.f) + 1e-5f);
    float rs = res_scale[0];
    #pragma unroll
    for (int j=0;j<6;j++){
        int d = lane + j*32;
        out[(size_t)d*LSEQ + l] = x[(size_t)d*LSEQ + l]
            + rs*((v[j]-mu)*inv*ln_g[d] + ln_b[d]);
    }
}

// ---------------- launch ----------------
extern "C" void kernel_launch(void* const* d_in, const int* in_sizes, int n_in,
                              void* d_out, int out_size){
    (void)in_sizes; (void)n_in; (void)out_size;
    const float* x        = (const float*)d_in[0];
    const float* w_in     = (const float*)d_in[1];
    const float* w_zx     = (const float*)d_in[2];
    const float* w_bc     = (const float*)d_in[3];
    const float* b_bc     = (const float*)d_in[4];
    const float* w_dt     = (const float*)d_in[5];
    const float* dt_bias  = (const float*)d_in[6];
    const float* A_log    = (const float*)d_in[7];
    const float* theta    = (const float*)d_in[8];
    const float* D_skip   = (const float*)d_in[9];
    const float* rms_w    = (const float*)d_in[10];
    const float* w_mout   = (const float*)d_in[11];
    const float* w_out    = (const float*)d_in[12];
    const float* ln_g     = (const float*)d_in[13];
    const float* ln_b     = (const float*)d_in[14];
    const float* resscale = (const float*)d_in[15];
    float* out = (float*)d_out;

    float *b_xseq,*b_proj,*b_xssmt,*b_wcomb,*b_winT,*b_wmoutT,*b_woutT,*b_zx;
    float *b_dtr,*b_dtb,*b_rb,*b_cum,*b_Bt,*b_Ct,*b_y,*b_g,*b_mo,*b_mT,*b_pre;
    float *b_rc,*b_hend,*b_hin;
    cudaGetSymbolAddress((void**)&b_xseq,  g_xseq);
    cudaGetSymbolAddress((void**)&b_proj,  g_proj);
    cudaGetSymbolAddress((void**)&b_xssmt, g_xssmt);
    cudaGetSymbolAddress((void**)&b_wcomb, g_wcomb);
    cudaGetSymbolAddress((void**)&b_winT,  g_winT);
    cudaGetSymbolAddress((void**)&b_wmoutT,g_wmoutT);
    cudaGetSymbolAddress((void**)&b_woutT, g_woutT);
    cudaGetSymbolAddress((void**)&b_zx,    g_zx);
    cudaGetSymbolAddress((void**)&b_dtr,   g_dtr);
    cudaGetSymbolAddress((void**)&b_dtb,   g_dtb);
    cudaGetSymbolAddress((void**)&b_rb,    g_rb);
    cudaGetSymbolAddress((void**)&b_cum,   g_cum);
    cudaGetSymbolAddress((void**)&b_Bt,    g_Bt);
    cudaGetSymbolAddress((void**)&b_Ct,    g_Ct);
    cudaGetSymbolAddress((void**)&b_y,     g_y);
    cudaGetSymbolAddress((void**)&b_g,     g_g);
    cudaGetSymbolAddress((void**)&b_mo,    g_mo);
    cudaGetSymbolAddress((void**)&b_mT,    g_mT);
    cudaGetSymbolAddress((void**)&b_pre,   g_pre);
    cudaGetSymbolAddress((void**)&b_rc,    g_rc);
    cudaGetSymbolAddress((void**)&b_hend,  g_hend);
    cudaGetSymbolAddress((void**)&b_hin,   g_hin);

    // 0: direction sequences + fused weight prep
    k_build<<<dim3(DIMC, KC), 256>>>(x, b_xseq);
    k_wprep<<<(WP4+255)/256, 256>>>(w_in, w_mout, w_out, w_zx, w_bc,
                                    b_winT, b_wmoutT, b_woutT, b_wcomb);
    // 1: proj = x_seq @ w_in
    k_gemm_tf32p<<<dim3(768/64, ROWS/128), 256>>>(b_xseq, b_winT, b_proj, ROWS, 768, DIMC);
    // 2: fused silu + dt GEMV
    k_silu_dt<<<ROWS/8, 256>>>(b_proj, w_dt, b_xssmt, b_dtr);
    // 3: zx/bc GEMM
    k_gemm_tf32p<<<dim3((ZXW+63)/64, ROWS/128), 256>>>(b_xssmt, b_wcomb, b_zx, ROWS, ZXW, EC);
    // 4: dt / r / cumsum
    k_dtscan<<<KC*HHC, 256>>>(b_dtr, dt_bias, A_log, b_dtb, b_rb, b_cum);
    // 5: rms + rotary
    k_rot<<<(ROWS+127)/128, 128>>>(b_zx, b_bc, theta, b_cum, b_Bt, b_Ct);
    // 6: split-sequence scan: local / combine / fixup
    k_scanA<<<dim3(KC*HHC, NSEG), 256>>>(b_Bt, b_Ct, b_zx, b_dtb, b_rb, D_skip, b_y, b_rc, b_hend);
    k_scanB<<<KC*HHC, 256>>>(b_hend, b_rc, b_hin);
    k_scanC<<<dim3(KC*HHC, NSEG), 256>>>(b_Ct, b_rc, b_hin, b_y);
    // 7: gated rms norm
    k_gate<<<(ROWS*32+255)/256, 256>>>(b_y, b_zx, rms_w, b_g);
    // 8: mamba out GEMM
    k_gemm_tf32p<<<dim3(EC/64, ROWS/128), 256>>>(b_g, b_wmoutT, b_mo, ROWS, EC, EC);
    // 9: fused gate-multiply + merge
    k_xmerge<<<(LSEQ*EC+255)/256, 256>>>(b_mo, b_proj, b_mT);
    // 10: output projection
    k_gemm_tf32p<<<dim3(DIMC/64, LSEQ/128), 256>>>(b_mT, b_woutT, b_pre, LSEQ, DIMC, EC);
    // 11: layernorm + residual
    k_ln<<<(LSEQ*32+255)/256, 256>>>(b_pre, x, ln_g, ln_b, resscale, out);
}

// round 6
// speedup vs baseline: 4.1027x; 1.1523x over previous
#include <cuda_runtime.h>
#include <cstdint>
#include <math.h>

#define LSEQ 2304
#define DIMC 192
#define EC   384
#define NC   16
#define PC   64
#define HHC  6
#define KC   4
#define ROWS (KC*LSEQ)   /* 9216 */
#define ZXW  800         /* 768 (zx) + 32 (bc); dt handled separately in fp32 */
#define NSEG 8
#define TSEG (LSEQ/NSEG) /* 288 */

// ---------------- scratch (static device globals; no allocation) ----------------
static __device__ __align__(16) float g_xseq[ROWS*DIMC];      // tf32-rounded
static __device__ __align__(16) float g_proj[ROWS*768];       // fp32
static __device__ __align__(16) float g_xssmt[ROWS*EC];       // tf32-rounded silu(proj)
static __device__ __align__(16) float g_wcomb[EC*ZXW];        // tf32-rounded
static __device__ __align__(16) float g_winT[DIMC*768];       // tf32-rounded
static __device__ __align__(16) float g_wmoutT[EC*EC];        // tf32-rounded
static __device__ __align__(16) float g_woutT[EC*DIMC];       // tf32-rounded
static __device__ __align__(16) float g_zx[(size_t)ROWS*ZXW]; // fp32
static __device__ __align__(16) float g_dtr[ROWS*HHC];
static __device__ __align__(16) float g_dtb[ROWS*HHC];        // 0.5*dt
static __device__ __align__(16) float g_rb[ROWS*HHC];
static __device__ __align__(16) float g_cum[ROWS*HHC];
static __device__ __align__(16) float g_Bt[ROWS*HHC*NC];
static __device__ __align__(16) float g_Ct[ROWS*HHC*NC];
static __device__ __align__(16) float g_y[ROWS*EC];
static __device__ __align__(16) float g_g[ROWS*EC];           // tf32-rounded
static __device__ __align__(16) float g_mo[ROWS*EC];
static __device__ __align__(16) float g_mT[LSEQ*EC];          // tf32-rounded
static __device__ __align__(16) float g_pre[LSEQ*DIMC];
static __device__ __align__(16) float g_rc[KC*HHC*LSEQ];
static __device__ __align__(16) float g_hend[KC*HHC*NSEG*PC*NC];
static __device__ __align__(16) float g_hin[KC*HHC*NSEG*PC*NC];

// fast silu: MUFU-based exp + fast divide. ~1e-6 rel err, far below tf32 noise.
__device__ __forceinline__ float siluf(float v){
    return __fdividef(v, 1.f + __expf(-v));
}

__device__ __forceinline__ float f2tf32f(float f){
    uint32_t u; asm("cvt.rna.tf32.f32 %0, %1;" : "=r"(u) : "f"(f));
    return __uint_as_float(u);
}

#define CP16(dst,src) asm volatile("cp.async.cg.shared.global [%0],[%1],16;\n"::"r"(dst),"l"(src))
#define CP16Z(dst,src) asm volatile("cp.async.cg.shared.global [%0],[%1],16,0;\n"::"r"(dst),"l"(src))
#define CP4(dst,src)  asm volatile("cp.async.ca.shared.global [%0],[%1],4;\n"::"r"(dst),"l"(src))
#define CPCOMMIT()    asm volatile("cp.async.commit_group;\n")
#define CPWAIT1()     asm volatile("cp.async.wait_group 1;\n")

// ---------------- K0: build 4-direction sequence (smem-staged, tf32 out) ----------------
__global__ __launch_bounds__(256) void k_build(const float* __restrict__ x, float* __restrict__ xseq){
    __shared__ float sm[LSEQ + LSEQ/48];
    int d = blockIdx.x;
    int k = blockIdx.y;
    int tid = threadIdx.x;
    for (int i = tid; i < LSEQ; i += 256)
        sm[i + i/48] = x[d*LSEQ + i];
    __syncthreads();
    size_t obase = (size_t)k*(LSEQ*DIMC) + (size_t)d*LSEQ;
    for (int l = tid; l < LSEQ; l += 256){
        int m;
        if      (k==0) m = l;
        else if (k==1) m = (l%48)*48 + l/48;
        else if (k==2) m = 2303 - l;
        else { int lr = 2303-l; m = (lr%48)*48 + lr/48; }
        xseq[obase + l] = f2tf32f(sm[m + m/48]);
    }
}

// ---------------- fused weight prep: tf32 copies of all weights ----------------
#define WP1 (DIMC*768)
#define WP2 (WP1 + EC*EC)
#define WP3 (WP2 + EC*DIMC)
#define WP4 (WP3 + EC*ZXW)
__global__ void k_wprep(const float* __restrict__ w_in, const float* __restrict__ w_mout,
                        const float* __restrict__ w_out, const float* __restrict__ wzx,
                        const float* __restrict__ wbc,
                        float* __restrict__ winT, float* __restrict__ wmoutT,
                        float* __restrict__ woutT, float* __restrict__ wcomb){
    int idx = blockIdx.x*blockDim.x + threadIdx.x;
    if (idx >= WP4) return;
    if (idx < WP1){ winT[idx] = f2tf32f(w_in[idx]); return; }
    if (idx < WP2){ int i = idx-WP1; wmoutT[i] = f2tf32f(w_mout[i]); return; }
    if (idx < WP3){ int i = idx-WP2; woutT[i] = f2tf32f(w_out[i]); return; }
    int i = idx-WP3;
    int kk = i / ZXW, j = i % ZXW;
    float v = (j < 768) ? wzx[kk*768 + j] : wbc[kk*32 + (j-768)];
    wcomb[i] = f2tf32f(v);
}

// ---------------- tf32 tensor-core GEMM, cp.async double-buffered ----------------
// BM=128, BN=128, BK=16. 8 warps: 2(m) x 4(n), warp tile 64x32, mma m16n8k8.
__global__ __launch_bounds__(256) void k_gemm_tf32p(const float* __restrict__ A,
                                                    const float* __restrict__ B,
                                                    float* __restrict__ C,
                                                    int M, int N, int K){
    const int BM=128, BN=128, BK=16;
    __shared__ __align__(16) float As[2][BM][BK+4];    // stride 20
    __shared__ __align__(16) float Bs[2][BK][BN+8];    // stride 136
    int tid  = threadIdx.x;
    int warp = tid>>5, lane = tid&31;
    int wm = warp>>2, wn = warp&3;      // 2 x 4 warp grid
    int gid = lane>>2, tig = lane&3;
    int bm = blockIdx.y*BM, bn = blockIdx.x*BN;

    float acc[4][4][4];
    #pragma unroll
    for (int m=0;m<4;m++)
        #pragma unroll
        for (int n=0;n<4;n++)
            #pragma unroll
            for (int i=0;i<4;i++) acc[m][n][i]=0.f;

    auto stage = [&](int buf, int k0){
        #pragma unroll
        for (int j=0;j<2;j++){
            int id = tid*2 + j;
            int r = id>>2, kc = id&3;
            uint32_t dst = (uint32_t)__cvta_generic_to_shared(&As[buf][r][kc*4]);
            const float* src = &A[(size_t)(bm+r)*K + k0 + kc*4];
            CP16(dst, src);
        }
        #pragma unroll
        for (int j=0;j<2;j++){
            int i = tid + j*256;
            int r = i>>5, c = i&31;
            uint32_t dst = (uint32_t)__cvta_generic_to_shared(&Bs[buf][r][c*4]);
            if (bn + c*4 + 4 <= N){
                const float* src = &B[(size_t)(k0+r)*N + bn + c*4];
                CP16(dst, src);
            } else {
                CP16Z(dst, B);
            }
        }
        CPCOMMIT();
    };

    int nk = K/BK;
    stage(0, 0);
    for (int kt=0; kt<nk; ++kt){
        int buf = kt&1;
        if (kt+1 < nk) stage(buf^1, (kt+1)*BK);
        else CPCOMMIT();
        CPWAIT1();
        __syncthreads();

        #pragma unroll
        for (int kk=0; kk<2; kk++){
            int kb = kk*8;
            uint32_t a[4][4];
            #pragma unroll
            for (int m=0;m<4;m++){
                int mr = wm*64 + m*16;
                a[m][0] = __float_as_uint(As[buf][mr+gid  ][kb+tig  ]);
                a[m][1] = __float_as_uint(As[buf][mr+gid+8][kb+tig  ]);
                a[m][2] = __float_as_uint(As[buf][mr+gid  ][kb+tig+4]);
                a[m][3] = __float_as_uint(As[buf][mr+gid+8][kb+tig+4]);
            }
            uint32_t b[4][2];
            #pragma unroll
            for (int n=0;n<4;n++){
                int nc = wn*32 + n*8;
                b[n][0] = __float_as_uint(Bs[buf][kb+tig  ][nc+gid]);
                b[n][1] = __float_as_uint(Bs[buf][kb+tig+4][nc+gid]);
            }
            #pragma unroll
            for (int m=0;m<4;m++)
                #pragma unroll
                for (int n=0;n<4;n++){
                    asm volatile(
                        "mma.sync.aligned.m16n8k8.row.col.f32.tf32.tf32.f32 "
                        "{%0,%1,%2,%3}, {%4,%5,%6,%7}, {%8,%9}, {%0,%1,%2,%3};"
                        : "+f"(acc[m][n][0]), "+f"(acc[m][n][1]),
                          "+f"(acc[m][n][2]), "+f"(acc[m][n][3])
                        : "r"(a[m][0]), "r"(a[m][1]), "r"(a[m][2]), "r"(a[m][3]),
                          "r"(b[n][0]), "r"(b[n][1]));
                }
        }
        __syncthreads();
    }
    #pragma unroll
    for (int m=0;m<4;m++){
        int row0 = bm + wm*64 + m*16 + gid;
        #pragma unroll
        for (int n=0;n<4;n++){
            int col = bn + wn*32 + n*8 + tig*2;
            if (col < N){
                C[(size_t)row0*N + col] = acc[m][n][0];
                C[(size_t)(row0+8)*N + col] = acc[m][n][2];
            }
            if (col+1 < N){
                C[(size_t)row0*N + col + 1] = acc[m][n][1];
                C[(size_t)(row0+8)*N + col + 1] = acc[m][n][3];
            }
        }
    }
}

// ---------------- fused: xssmt = tf32(silu(proj)), dtr = silu(proj)·w_dt (fp32) ----------------
__global__ __launch_bounds__(256) void k_silu_dt(const float* __restrict__ proj,
                                                 const float* __restrict__ w_dt,
                                                 float* __restrict__ xssmt,
                                                 float* __restrict__ dtr){
    __shared__ float ws[EC*HHC];
    int tid = threadIdx.x;
    for (int i=tid; i<EC*HHC; i+=256) ws[i] = w_dt[i];
    __syncthreads();
    int warp = tid>>5, lane = tid&31;
    int row = blockIdx.x*8 + warp;
    float s[HHC];
    #pragma unroll
    for (int h=0;h<HHC;h++) s[h]=0.f;
    #pragma unroll
    for (int j=0;j<12;j++){
        int e = lane + j*32;
        float xv = siluf(proj[(size_t)row*768 + e]);
        xssmt[(size_t)row*EC + e] = f2tf32f(xv);
        #pragma unroll
        for (int h=0;h<HHC;h++) s[h] = fmaf(xv, ws[e*HHC+h], s[h]);
    }
    #pragma unroll
    for (int h=0;h<HHC;h++){
        #pragma unroll
        for (int off=16; off>=1; off>>=1) s[h] += __shfl_xor_sync(0xffffffffu, s[h], off);
    }
    #pragma unroll
    for (int h=0;h<HHC;h++)
        if (lane == h) dtr[(size_t)row*HHC + h] = s[h];
}

// ---------------- dt path: softplus, r, cumsum (precise exp kept here) ----------------
__global__ void k_dtscan(const float* __restrict__ dtr, const float* __restrict__ dt_bias,
                         const float* __restrict__ A_log,
                         float* __restrict__ dtb, float* __restrict__ rb, float* __restrict__ cumb){
    int k = blockIdx.x / HHC, h = blockIdx.x % HHC;
    __shared__ float part[256];
    float expA = expf(A_log[h]);
    float bias = dt_bias[h];
    int tid = threadIdx.x;
    int tbase = tid*9;
    float loc[9]; float s = 0.f;
    #pragma unroll
    for (int i=0;i<9;i++){
        size_t row = (size_t)k*LSEQ + tbase + i;
        float v  = dtr[row*HHC + h] + bias;
        float dt = (v > 20.f) ? v : log1pf(expf(v));
        dtb[row*HHC+h] = 0.5f*dt;
        rb [row*HHC+h] = expf(-dt*expA);
        s += dt; loc[i] = s;
    }
    part[tid] = s; __syncthreads();
    for (int off=1; off<256; off<<=1){
        float add = (tid >= off) ? part[tid-off] : 0.f;
        __syncthreads();
        part[tid] += add;
        __syncthreads();
    }
    float offset = part[tid] - s;
    #pragma unroll
    for (int i=0;i<9;i++){
        size_t row = (size_t)k*LSEQ + tbase + i;
        cumb[row*HHC+h] = loc[i] + offset;
    }
}

// ---------------- rms(B/C) + rotary: warp per row, coalesced writes ----------------
__global__ __launch_bounds__(256) void k_rot(const float* __restrict__ zx, const float* __restrict__ b_bc,
                                             const float* __restrict__ theta, const float* __restrict__ cumb,
                                             float* __restrict__ Bt, float* __restrict__ Ct){
    int row  = (blockIdx.x*blockDim.x + threadIdx.x) >> 5;
    int lane = threadIdx.x & 31;
    if (row >= ROWS) return;
    // lanes 0-15: B components, lanes 16-31: C components
    float bc = zx[(size_t)row*ZXW + 768 + lane] + b_bc[lane];
    float s = bc*bc;
    s += __shfl_xor_sync(0xffffffffu, s, 1);
    s += __shfl_xor_sync(0xffffffffu, s, 2);
    s += __shfl_xor_sync(0xffffffffu, s, 4);
    s += __shfl_xor_sync(0xffffffffu, s, 8);
    float rn = rsqrtf(s*(1.f/16.f) + 1e-6f);
    float v = bc * rn;
    int j = lane & 15;
    int half = lane & 16;
    int i = j >> 1;
    float v0 = __shfl_sync(0xffffffffu, v, half + 2*i);
    float v1 = __shfl_sync(0xffffffffu, v, half + 2*i + 1);
    bool odd = (j & 1) != 0;
    float th = theta[0]; // placeholder init (overwritten each h)
    #pragma unroll
    for (int h=0; h<HHC; h++){
        float cd = cumb[(size_t)row*HHC + h];
        th = theta[h*8 + i];
        float ss, cc;
        sincosf(cd*th, &ss, &cc);
        float o = odd ? fmaf(-v0, ss, v1*cc) : fmaf(v0, cc, v1*ss);
        float* dst = half ? Ct : Bt;
        dst[((size_t)row*HHC + h)*16 + j] = o;
    }
}

// ---------------- scan phase A: per-segment local scan (h_in = 0) ----------------
#define SCH 32
__global__ __launch_bounds__(256) void k_scanA(const float* __restrict__ Bt, const float* __restrict__ Ct,
                                               const float* __restrict__ zx, const float* __restrict__ dtb,
                                               const float* __restrict__ rb, const float* __restrict__ Dsk,
                                               float* __restrict__ y, float* __restrict__ rc,
                                               float* __restrict__ hend){
    __shared__ __align__(16) float Bs[2][SCH][16];
    __shared__ __align__(16) float Cs[2][SCH][16];
    __shared__ __align__(16) float Xs[2][SCH][64];
    __shared__ float Ds[2][SCH];
    __shared__ float Rs[2][SCH];
    __shared__ __align__(16) float Ys[SCH][64];
    __shared__ float Rys[SCH];

    int kh = blockIdx.x; int k = kh/HHC, h = kh%HHC;
    int seg = blockIdx.y;
    int tseg0 = seg*TSEG;
    int tid = threadIdx.x;
    int p = tid>>2, ng = tid&3;
    size_t bBase = ((size_t)k*LSEQ*HHC + h)*16;
    size_t xBase = (size_t)k*LSEQ*ZXW + 384 + (size_t)h*64;
    size_t sBase = (size_t)k*LSEQ*HHC + h;
    float dsk = Dsk[h];
    float* ybase = y + (size_t)k*LSEQ*EC + h*64;
    size_t rcBase = (size_t)kh*LSEQ;

    auto stage = [&](int buf, int t0){
        {
            int id = tid & 127;
            int tl = id>>2, sg = id&3;
            size_t off = bBase + (size_t)(t0+tl)*96 + sg*4;
            if (tid < 128){
                uint32_t d = (uint32_t)__cvta_generic_to_shared(&Bs[buf][tl][sg*4]);
                CP16(d, &Bt[off]);
            } else {
                uint32_t d = (uint32_t)__cvta_generic_to_shared(&Cs[buf][tl][sg*4]);
                CP16(d, &Ct[off]);
            }
        }
        #pragma unroll
        for (int j=0;j<2;j++){
            int i = tid + j*256;
            int tl = i>>4, c = i&15;
            uint32_t d = (uint32_t)__cvta_generic_to_shared(&Xs[buf][tl][c*4]);
            CP16(d, &zx[xBase + (size_t)(t0+tl)*ZXW + c*4]);
        }
        if (tid < SCH){
            uint32_t d = (uint32_t)__cvta_generic_to_shared(&Ds[buf][tid]);
            CP4(d, &dtb[sBase + (size_t)(t0+tid)*HHC]);
        } else if (tid < 2*SCH){
            int tl = tid - SCH;
            uint32_t d = (uint32_t)__cvta_generic_to_shared(&Rs[buf][tl]);
            CP4(d, &rb[sBase + (size_t)(t0+tl)*HHC]);
        }
        CPCOMMIT();
    };

    float hs0=0.f,hs1=0.f,hs2=0.f,hs3=0.f;
    float bx0=0.f,bx1=0.f,bx2=0.f,bx3=0.f;
    if (seg > 0){
        int tp = tseg0 - 1;
        float4 Bp = *(const float4*)&Bt[bBase + (size_t)tp*96 + ng*4];
        float xp = zx[xBase + (size_t)tp*ZXW + p];
        bx0 = Bp.x*xp; bx1 = Bp.y*xp; bx2 = Bp.z*xp; bx3 = Bp.w*xp;
    }
    float rp = 1.f;

    stage(0, tseg0);
    const int NCHUNK = TSEG/SCH;   // 9
    for (int c=0; c<NCHUNK; ++c){
        int buf = c&1;
        if (c+1 < NCHUNK) stage(buf^1, tseg0 + (c+1)*SCH);
        else CPCOMMIT();
        CPWAIT1();
        __syncthreads();

        #pragma unroll 4
        for (int t=0; t<SCH; ++t){
            float4 Bv = *(const float4*)&Bs[buf][t][ng*4];
            float4 Cv = *(const float4*)&Cs[buf][t][ng*4];
            float xv = Xs[buf][t][p];
            float ad = Ds[buf][t];
            float rv = Rs[buf][t];
            float G0 = Bv.x*xv, G1 = Bv.y*xv, G2 = Bv.z*xv, G3 = Bv.w*xv;
            float u0 = fmaf(rv,bx0,G0), u1 = fmaf(rv,bx1,G1);
            float u2 = fmaf(rv,bx2,G2), u3 = fmaf(rv,bx3,G3);
            hs0 = fmaf(rv,hs0,ad*u0); hs1 = fmaf(rv,hs1,ad*u1);
            hs2 = fmaf(rv,hs2,ad*u2); hs3 = fmaf(rv,hs3,ad*u3);
            bx0=G0; bx1=G1; bx2=G2; bx3=G3;
            rp *= rv;
            float v = fmaf(Cv.x,hs0, fmaf(Cv.y,hs1, fmaf(Cv.z,hs2, Cv.w*hs3)));
            v += __shfl_xor_sync(0xffffffffu, v, 1);
            v += __shfl_xor_sync(0xffffffffu, v, 2);
            if (ng == 0) Ys[t][p] = fmaf(dsk, xv, v);
            if (tid == 0) Rys[t] = rp;
        }
        __syncthreads();
        int t0 = tseg0 + c*SCH;
        #pragma unroll
        for (int j=0;j<2;j++){
            int i = tid + j*256;
            int tl = i>>4, cc = i&15;
            *(float4*)&ybase[(size_t)(t0+tl)*EC + cc*4] = *(const float4*)&Ys[tl][cc*4];
        }
        if (tid < SCH) rc[rcBase + t0 + tid] = Rys[tid];
    }
    float4 he = make_float4(hs0,hs1,hs2,hs3);
    *(float4*)&hend[(((size_t)kh*NSEG + seg)*PC + p)*NC + ng*4] = he;
}

// ---------------- scan phase B: sequential combine of segment boundary states ----------------
__global__ __launch_bounds__(256) void k_scanB(const float* __restrict__ hend,
                                               const float* __restrict__ rc,
                                               float* __restrict__ hin){
    int kh = blockIdx.x;
    int tid = threadIdx.x;
    int p = tid>>2, ng = tid&3;
    float4 hi = make_float4(0.f,0.f,0.f,0.f);
    #pragma unroll
    for (int s=0; s<NSEG; ++s){
        size_t idx = (((size_t)kh*NSEG + s)*PC + p)*NC + ng*4;
        *(float4*)&hin[idx] = hi;
        float4 he = *(const float4*)&hend[idx];
        float Rseg = rc[(size_t)kh*LSEQ + s*TSEG + TSEG-1];
        hi.x = fmaf(Rseg, hi.x, he.x);
        hi.y = fmaf(Rseg, hi.y, he.y);
        hi.z = fmaf(Rseg, hi.z, he.z);
        hi.w = fmaf(Rseg, hi.w, he.w);
    }
}

// ---------------- scan phase C: fixup y += R(t) * (C_t · h_in) ----------------
__global__ __launch_bounds__(256) void k_scanC(const float* __restrict__ Ct,
                                               const float* __restrict__ rc,
                                               const float* __restrict__ hin,
                                               float* __restrict__ y){
    int seg = blockIdx.y;
    if (seg == 0) return;
    __shared__ float Hs[PC][NC+1];
    __shared__ float Cs[SCH][NC+1];
    __shared__ float Rsh[SCH];
    int kh = blockIdx.x; int k = kh/HHC, h = kh%HHC;
    int tid = threadIdx.x;
    int p = tid&63, tq = tid>>6;
    size_t hBase = ((size_t)kh*NSEG + seg)*PC*NC;
    for (int i=tid; i<PC*NC; i+=256) Hs[i>>4][i&15] = hin[hBase + i];
    __syncthreads();
    float hn[NC];
    #pragma unroll
    for (int i=0;i<NC;i++) hn[i] = Hs[p][i];

    size_t bBase = ((size_t)k*LSEQ*HHC + h)*16;
    size_t rcBase = (size_t)kh*LSEQ;
    float* ybase = y + (size_t)k*LSEQ*EC + h*64;
    int tseg0 = seg*TSEG;

    for (int c=0; c<TSEG/SCH; ++c){
        int t0 = tseg0 + c*SCH;
        for (int i=tid; i<SCH*NC; i+=256){
            int tl = i>>4, nn = i&15;
            Cs[tl][nn] = Ct[bBase + (size_t)(t0+tl)*96 + nn];
        }
        if (tid < SCH) Rsh[tid] = rc[rcBase + t0 + tid];
        __syncthreads();
        if (Rsh[0] == 0.f) break;
        #pragma unroll
        for (int jt=0; jt<SCH/4; ++jt){
            int tl = tq + jt*4;
            float R = Rsh[tl];
            if (R != 0.f){
                float corr = 0.f;
                #pragma unroll
                for (int i=0;i<NC;i++) corr = fmaf(Cs[tl][i], hn[i], corr);
                ybase[(size_t)(t0+tl)*EC + p] += R*corr;
            }
        }
        __syncthreads();
    }
}

// ---------------- g = tf32(rms(y * silu(z)) * rms_w)  (warp per row) ----------------
__global__ void k_gate(const float* __restrict__ y, const float* __restrict__ zx,
                       const float* __restrict__ rms_w, float* __restrict__ g){
    int warp = (blockIdx.x*blockDim.x + threadIdx.x) >> 5;
    int lane = threadIdx.x & 31;
    if (warp >= ROWS) return;
    size_t ybase = (size_t)warp*EC;
    size_t zbase = (size_t)warp*ZXW;
    float v[12]; float s2 = 0.f;
    #pragma unroll
    for (int j=0;j<12;j++){
        int e = lane + j*32;
        float z = zx[zbase + e];
        float t = y[ybase + e] * siluf(z);
        v[j] = t; s2 += t*t;
    }
    #pragma unroll
    for (int off=16; off>=1; off>>=1) s2 += __shfl_xor_sync(0xffffffffu, s2, off);
    float rn = rsqrtf(s2*(1.f/384.f) + 1e-6f);
    #pragma unroll
    for (int j=0;j<12;j++){
        int e = lane + j*32;
        g[ybase + e] = f2tf32f(v[j]*rn*rms_w[e]);
    }
}

// ---------------- fused: x_out = mo * silu(gate); merge 4 dirs -> mT (tf32) ----------------
__global__ void k_xmerge(const float* __restrict__ mo, const float* __restrict__ proj,
                         float* __restrict__ mT){
    int idx = blockIdx.x*blockDim.x + threadIdx.x;
    if (idx >= LSEQ*EC) return;
    int l = idx / EC, e = idx % EC;
    int lt = (l%48)*48 + l/48;
    int r0 = l;
    int r1 = LSEQ + lt;
    int r2 = 2*LSEQ + 2303 - l;
    int r3 = 3*LSEQ + 2303 - lt;
    float v = mo[(size_t)r0*EC+e] * siluf(proj[(size_t)r0*768 + 384 + e])
            + mo[(size_t)r1*EC+e] * siluf(proj[(size_t)r1*768 + 384 + e])
            + mo[(size_t)r2*EC+e] * siluf(proj[(size_t)r2*768 + 384 + e])
            + mo[(size_t)r3*EC+e] * siluf(proj[(size_t)r3*768 + 384 + e]);
    mT[idx] = f2tf32f(v);
}

// ---------------- LayerNorm + residual ----------------
__global__ void k_ln(const float* __restrict__ pre, const float* __restrict__ x,
                     const float* __restrict__ ln_g, const float* __restrict__ ln_b,
                     const float* __restrict__ res_scale, float* __restrict__ out){
    int warp = (blockIdx.x*blockDim.x + threadIdx.x) >> 5;
    int lane = threadIdx.x & 31;
    if (warp >= LSEQ) return;
    int l = warp;
    float v[6]; float s = 0.f;
    #pragma unroll
    for (int j=0;j<6;j++){ v[j] = pre[(size_t)l*DIMC + lane + j*32]; s += v[j]; }
    #pragma unroll
    for (int off=16; off>=1; off>>=1) s += __shfl_xor_sync(0xffffffffu, s, off);
    float mu = s*(1.f/192.f);
    float q = 0.f;
    #pragma unroll
    for (int j=0;j<6;j++){ float d = v[j]-mu; q += d*d; }
    #pragma unroll
    for (int off=16; off>=1; off>>=1) q += __shfl_xor_sync(0xffffffffu, q, off);
    float inv = rsqrtf(q*(1.f/192.f) + 1e-5f);
    float rs = res_scale[0];
    #pragma unroll
    for (int j=0;j<6;j++){
        int d = lane + j*32;
        out[(size_t)d*LSEQ + l] = x[(size_t)d*LSEQ + l]
            + rs*((v[j]-mu)*inv*ln_g[d] + ln_b[d]);
    }
}

// ---------------- launch ----------------
extern "C" void kernel_launch(void* const* d_in, const int* in_sizes, int n_in,
                              void* d_out, int out_size){
    (void)in_sizes; (void)n_in; (void)out_size;
    const float* x        = (const float*)d_in[0];
    const float* w_in     = (const float*)d_in[1];
    const float* w_zx     = (const float*)d_in[2];
    const float* w_bc     = (const float*)d_in[3];
    const float* b_bc     = (const float*)d_in[4];
    const float* w_dt     = (const float*)d_in[5];
    const float* dt_bias  = (const float*)d_in[6];
    const float* A_log    = (const float*)d_in[7];
    const float* theta    = (const float*)d_in[8];
    const float* D_skip   = (const float*)d_in[9];
    const float* rms_w    = (const float*)d_in[10];
    const float* w_mout   = (const float*)d_in[11];
    const float* w_out    = (const float*)d_in[12];
    const float* ln_g     = (const float*)d_in[13];
    const float* ln_b     = (const float*)d_in[14];
    const float* resscale = (const float*)d_in[15];
    float* out = (float*)d_out;

    float *b_xseq,*b_proj,*b_xssmt,*b_wcomb,*b_winT,*b_wmoutT,*b_woutT,*b_zx;
    float *b_dtr,*b_dtb,*b_rb,*b_cum,*b_Bt,*b_Ct,*b_y,*b_g,*b_mo,*b_mT,*b_pre;
    float *b_rc,*b_hend,*b_hin;
    cudaGetSymbolAddress((void**)&b_xseq,  g_xseq);
    cudaGetSymbolAddress((void**)&b_proj,  g_proj);
    cudaGetSymbolAddress((void**)&b_xssmt, g_xssmt);
    cudaGetSymbolAddress((void**)&b_wcomb, g_wcomb);
    cudaGetSymbolAddress((void**)&b_winT,  g_winT);
    cudaGetSymbolAddress((void**)&b_wmoutT,g_wmoutT);
    cudaGetSymbolAddress((void**)&b_woutT, g_woutT);
    cudaGetSymbolAddress((void**)&b_zx,    g_zx);
    cudaGetSymbolAddress((void**)&b_dtr,   g_dtr);
    cudaGetSymbolAddress((void**)&b_dtb,   g_dtb);
    cudaGetSymbolAddress((void**)&b_rb,    g_rb);
    cudaGetSymbolAddress((void**)&b_cum,   g_cum);
    cudaGetSymbolAddress((void**)&b_Bt,    g_Bt);
    cudaGetSymbolAddress((void**)&b_Ct,    g_Ct);
    cudaGetSymbolAddress((void**)&b_y,     g_y);
    cudaGetSymbolAddress((void**)&b_g,     g_g);
    cudaGetSymbolAddress((void**)&b_mo,    g_mo);
    cudaGetSymbolAddress((void**)&b_mT,    g_mT);
    cudaGetSymbolAddress((void**)&b_pre,   g_pre);
    cudaGetSymbolAddress((void**)&b_rc,    g_rc);
    cudaGetSymbolAddress((void**)&b_hend,  g_hend);
    cudaGetSymbolAddress((void**)&b_hin,   g_hin);

    k_build<<<dim3(DIMC, KC), 256>>>(x, b_xseq);
    k_wprep<<<(WP4+255)/256, 256>>>(w_in, w_mout, w_out, w_zx, w_bc,
                                    b_winT, b_wmoutT, b_woutT, b_wcomb);
    // proj = x_seq @ w_in (9216 x 768 x 192)
    k_gemm_tf32p<<<dim3(768/128, ROWS/128), 256>>>(b_xseq, b_winT, b_proj, ROWS, 768, DIMC);
    // fused silu + dt GEMV
    k_silu_dt<<<ROWS/8, 256>>>(b_proj, w_dt, b_xssmt, b_dtr);
    // zx/bc GEMM (9216 x 800 x 384)
    k_gemm_tf32p<<<dim3((ZXW+127)/128, ROWS/128), 256>>>(b_xssmt, b_wcomb, b_zx, ROWS, ZXW, EC);
    // dt / r / cumsum
    k_dtscan<<<KC*HHC, 256>>>(b_dtr, dt_bias, A_log, b_dtb, b_rb, b_cum);
    // rms + rotary (warp per row)
    k_rot<<<ROWS/8, 256>>>(b_zx, b_bc, theta, b_cum, b_Bt, b_Ct);
    // split-sequence scan
    k_scanA<<<dim3(KC*HHC, NSEG), 256>>>(b_Bt, b_Ct, b_zx, b_dtb, b_rb, D_skip, b_y, b_rc, b_hend);
    k_scanB<<<KC*HHC, 256>>>(b_hend, b_rc, b_hin);
    k_scanC<<<dim3(KC*HHC, NSEG), 256>>>(b_Ct, b_rc, b_hin, b_y);
    // gated rms norm
    k_gate<<<(ROWS*32+255)/256, 256>>>(b_y, b_zx, rms_w, b_g);
    // mamba out GEMM (9216 x 384 x 384)
    k_gemm_tf32p<<<dim3(EC/128, ROWS/128), 256>>>(b_g, b_wmoutT, b_mo, ROWS, EC, EC);
    // fused gate-multiply + merge
    k_xmerge<<<(LSEQ*EC+255)/256, 256>>>(b_mo, b_proj, b_mT);
    // output projection GEMM (2304 x 192 x 384)
    k_gemm_tf32p<<<dim3((DIMC+127)/128, LSEQ/128), 256>>>(b_mT, b_woutT, b_pre, LSEQ, DIMC, EC);
    // layernorm + residual
    k_ln<<<(LSEQ*32+255)/256, 256>>>(b_pre, x, ln_g, ln_b, resscale, out);
}

// round 7
// speedup vs baseline: 4.3307x; 1.0555x over previous
#include <cuda_runtime.h>
#include <cstdint>
#include <math.h>

#define LSEQ 2304
#define DIMC 192
#define EC   384
#define NC   16
#define PC   64
#define HHC  6
#define KC   4
#define ROWS (KC*LSEQ)   /* 9216 */
#define ZXW  800         /* zx GEMM logical N: 384 z + 384 xh + 32 bc */
#define NSEG 8
#define TSEG (LSEQ/NSEG) /* 288 */

// ---------------- scratch (static device globals; no allocation) ----------------
static __device__ __align__(16) float g_xseq[ROWS*DIMC];      // tf32-rounded
static __device__ __align__(16) float g_proj[ROWS*768];       // fp32
static __device__ __align__(16) float g_xssmt[ROWS*EC];       // tf32 silu(proj) (GEMM epi)
static __device__ __align__(16) float g_wcomb[EC*ZXW];        // tf32-rounded
static __device__ __align__(16) float g_winT[DIMC*768];       // tf32-rounded
static __device__ __align__(16) float g_wmoutT[EC*EC];        // tf32-rounded
static __device__ __align__(16) float g_woutT[EC*DIMC];       // tf32-rounded
static __device__ __align__(16) float g_z  [ROWS*EC];         // fp32 (zx epi split)
static __device__ __align__(16) float g_xh [ROWS*EC];         // fp32
static __device__ __align__(16) float g_bcb[ROWS*32];         // fp32
static __device__ __align__(16) float g_dtr[ROWS*HHC];
static __device__ __align__(16) float g_dtb[ROWS*HHC];        // 0.5*dt
static __device__ __align__(16) float g_rb[ROWS*HHC];
static __device__ __align__(16) float g_cum[ROWS*HHC];
static __device__ __align__(16) float g_Bt[ROWS*HHC*NC];
static __device__ __align__(16) float g_Ct[ROWS*HHC*NC];
static __device__ __align__(16) float g_y[ROWS*EC];
static __device__ __align__(16) float g_g[ROWS*EC];           // tf32-rounded
static __device__ __align__(16) float g_mo[ROWS*EC];
static __device__ __align__(16) float g_mT[LSEQ*EC];          // tf32-rounded
static __device__ __align__(16) float g_pre[LSEQ*DIMC];
static __device__ __align__(16) float g_rc[KC*HHC*LSEQ];
static __device__ __align__(16) float g_hend[KC*HHC*NSEG*PC*NC];
static __device__ __align__(16) float g_hin[KC*HHC*NSEG*PC*NC];

__device__ __forceinline__ float siluf(float v){
    return __fdividef(v, 1.f + __expf(-v));
}
__device__ __forceinline__ float f2tf32f(float f){
    uint32_t u; asm("cvt.rna.tf32.f32 %0, %1;" : "=r"(u) : "f"(f));
    return __uint_as_float(u);
}

#define CP16(dst,src) asm volatile("cp.async.cg.shared.global [%0],[%1],16;\n"::"r"(dst),"l"(src))
#define CP16Z(dst,src) asm volatile("cp.async.cg.shared.global [%0],[%1],16,0;\n"::"r"(dst),"l"(src))
#define CP4(dst,src)  asm volatile("cp.async.ca.shared.global [%0],[%1],4;\n"::"r"(dst),"l"(src))
#define CPCOMMIT()    asm volatile("cp.async.commit_group;\n")
#define CPWAIT1()     asm volatile("cp.async.wait_group 1;\n")

// ---------------- fused prep: build 4-dir sequence + tf32 weight copies ----------------
#define WP1 (DIMC*768)
#define WP2 (WP1 + EC*EC)
#define WP3 (WP2 + EC*DIMC)
#define WP4 (WP3 + EC*ZXW)
#define PREP_BUILD_BLKS (DIMC*KC)   /* 768 */
#define PREP_W_BLKS ((WP4+255)/256)
__global__ __launch_bounds__(256) void k_prep(const float* __restrict__ x, float* __restrict__ xseq,
                        const float* __restrict__ w_in, const float* __restrict__ w_mout,
                        const float* __restrict__ w_out, const float* __restrict__ wzx,
                        const float* __restrict__ wbc,
                        float* __restrict__ winT, float* __restrict__ wmoutT,
                        float* __restrict__ woutT, float* __restrict__ wcomb){
    int tid = threadIdx.x;
    if (blockIdx.x < PREP_BUILD_BLKS){
        __shared__ float sm[LSEQ + LSEQ/48];
        int d = blockIdx.x >> 2;
        int k = blockIdx.x & 3;
        for (int i = tid; i < LSEQ; i += 256)
            sm[i + i/48] = x[d*LSEQ + i];
        __syncthreads();
        size_t obase = (size_t)k*(LSEQ*DIMC) + (size_t)d*LSEQ;
        for (int l = tid; l < LSEQ; l += 256){
            int m;
            if      (k==0) m = l;
            else if (k==1) m = (l%48)*48 + l/48;
            else if (k==2) m = 2303 - l;
            else { int lr = 2303-l; m = (lr%48)*48 + lr/48; }
            xseq[obase + l] = f2tf32f(sm[m + m/48]);
        }
        return;
    }
    int idx = (blockIdx.x - PREP_BUILD_BLKS)*256 + tid;
    if (idx >= WP4) return;
    if (idx < WP1){ winT[idx] = f2tf32f(w_in[idx]); return; }
    if (idx < WP2){ int i = idx-WP1; wmoutT[i] = f2tf32f(w_mout[i]); return; }
    if (idx < WP3){ int i = idx-WP2; woutT[i] = f2tf32f(w_out[i]); return; }
    int i = idx-WP3;
    int kk = i / ZXW, j = i % ZXW;
    float v = (j < 768) ? wzx[kk*768 + j] : wbc[kk*32 + (j-768)];
    wcomb[i] = f2tf32f(v);
}

// ---------------- tf32 tensor-core GEMM, BK=32, cp.async double-buffered ----------------
// BM=128, BN=128, BK=32. 8 warps: 2(m) x 4(n), warp tile 64x32, mma m16n8k8.
// Dynamic smem: As[2][128][36] then Bs[2][32][136].
// EPI 0: plain C. EPI 1: proj + (col<384 -> o1 = tf32(silu)). EPI 2: split z/xh/bc, no C.
#define GEMM_SMEM ((2*128*36 + 2*32*136)*4)
#define AS(b,r,c) Asp[(b)*128*36 + (r)*36 + (c)]
#define BS(b,r,c) Bsp[(b)*32*136 + (r)*136 + (c)]
template<int EPI>
__global__ __launch_bounds__(256,2) void k_gemm(const float* __restrict__ A,
                                                const float* __restrict__ B,
                                                float* __restrict__ C,
                                                int M, int N, int K,
                                                float* __restrict__ o1,
                                                float* __restrict__ o2,
                                                float* __restrict__ o3){
    extern __shared__ float dynsmem[];
    float* Asp = dynsmem;
    float* Bsp = dynsmem + 2*128*36;
    const int BM=128, BN=128, BK=32;
    int tid  = threadIdx.x;
    int warp = tid>>5, lane = tid&31;
    int wm = warp>>2, wn = warp&3;
    int gid = lane>>2, tig = lane&3;
    int bm = blockIdx.y*BM, bn = blockIdx.x*BN;

    float acc[4][4][4];
    #pragma unroll
    for (int m=0;m<4;m++)
        #pragma unroll
        for (int n=0;n<4;n++)
            #pragma unroll
            for (int i=0;i<4;i++) acc[m][n][i]=0.f;

    auto stage = [&](int buf, int k0){
        #pragma unroll
        for (int j=0;j<4;j++){
            int i = tid + j*256;          // A: 128x32 = 1024 float4
            int r = i>>3, kc = i&7;
            uint32_t dst = (uint32_t)__cvta_generic_to_shared(&AS(buf, r, kc*4));
            CP16(dst, &A[(size_t)(bm+r)*K + k0 + kc*4]);
        }
        #pragma unroll
        for (int j=0;j<4;j++){
            int i = tid + j*256;          // B: 32x128 = 1024 float4
            int r = i>>5, c = i&31;
            uint32_t dst = (uint32_t)__cvta_generic_to_shared(&BS(buf, r, c*4));
            if (bn + c*4 + 4 <= N) CP16(dst, &B[(size_t)(k0+r)*N + bn + c*4]);
            else                   CP16Z(dst, B);
        }
        CPCOMMIT();
    };

    int nk = K/BK;
    stage(0, 0);
    for (int kt=0; kt<nk; ++kt){
        int buf = kt&1;
        if (kt+1 < nk) stage(buf^1, (kt+1)*BK);
        else CPCOMMIT();
        CPWAIT1();
        __syncthreads();

        #pragma unroll
        for (int kk=0; kk<4; kk++){
            int kb = kk*8;
            uint32_t a[4][4];
            #pragma unroll
            for (int m=0;m<4;m++){
                int mr = wm*64 + m*16;
                a[m][0] = __float_as_uint(AS(buf, mr+gid,   kb+tig  ));
                a[m][1] = __float_as_uint(AS(buf, mr+gid+8, kb+tig  ));
                a[m][2] = __float_as_uint(AS(buf, mr+gid,   kb+tig+4));
                a[m][3] = __float_as_uint(AS(buf, mr+gid+8, kb+tig+4));
            }
            uint32_t b[4][2];
            #pragma unroll
            for (int n=0;n<4;n++){
                int nc = wn*32 + n*8;
                b[n][0] = __float_as_uint(BS(buf, kb+tig,   nc+gid));
                b[n][1] = __float_as_uint(BS(buf, kb+tig+4, nc+gid));
            }
            #pragma unroll
            for (int m=0;m<4;m++)
                #pragma unroll
                for (int n=0;n<4;n++){
                    asm volatile(
                        "mma.sync.aligned.m16n8k8.row.col.f32.tf32.tf32.f32 "
                        "{%0,%1,%2,%3}, {%4,%5,%6,%7}, {%8,%9}, {%0,%1,%2,%3};"
                        : "+f"(acc[m][n][0]), "+f"(acc[m][n][1]),
                          "+f"(acc[m][n][2]), "+f"(acc[m][n][3])
                        : "r"(a[m][0]), "r"(a[m][1]), "r"(a[m][2]), "r"(a[m][3]),
                          "r"(b[n][0]), "r"(b[n][1]));
                }
        }
        __syncthreads();
    }
    #pragma unroll
    for (int m=0;m<4;m++){
        int row0 = bm + wm*64 + m*16 + gid;
        #pragma unroll
        for (int n=0;n<4;n++){
            int col = bn + wn*32 + n*8 + tig*2;
            #pragma unroll
            for (int cc=0; cc<2; cc++){
                int cl = col + cc;
                if (cl >= N) continue;
                float v0 = acc[m][n][cc];       // row0
                float v1 = acc[m][n][2+cc];     // row0+8
                if (EPI == 0){
                    C[(size_t)row0*N + cl] = v0;
                    C[(size_t)(row0+8)*N + cl] = v1;
                } else if (EPI == 1){
                    C[(size_t)row0*N + cl] = v0;
                    C[(size_t)(row0+8)*N + cl] = v1;
                    if (cl < 384){
                        o1[(size_t)row0*EC + cl] = f2tf32f(siluf(v0));
                        o1[(size_t)(row0+8)*EC + cl] = f2tf32f(siluf(v1));
                    }
                } else {  // EPI == 2: split z / xh / bc
                    if (cl < 384){
                        o1[(size_t)row0*EC + cl] = v0;
                        o1[(size_t)(row0+8)*EC + cl] = v1;
                    } else if (cl < 768){
                        o2[(size_t)row0*EC + cl-384] = v0;
                        o2[(size_t)(row0+8)*EC + cl-384] = v1;
                    } else {
                        o3[(size_t)row0*32 + cl-768] = v0;
                        o3[(size_t)(row0+8)*32 + cl-768] = v1;
                    }
                }
            }
        }
    }
}

// ---------------- dt GEMV: dtr[row][h] = silu(proj[row,:384])·w_dt[:,h] (fp32) ----------------
__global__ __launch_bounds__(256) void k_dtgemv(const float* __restrict__ proj,
                                                const float* __restrict__ w_dt,
                                                float* __restrict__ dtr){
    __shared__ float wst[HHC*EC];   // transposed [h][e] -> bank = lane, conflict-free
    int tid = threadIdx.x;
    for (int i=tid; i<EC*HHC; i+=256){
        int h = i % HHC, e = i / HHC;
        wst[h*EC + e] = w_dt[i];
    }
    __syncthreads();
    int warp = tid>>5, lane = tid&31;
    int row = blockIdx.x*8 + warp;
    float s[HHC];
    #pragma unroll
    for (int h=0;h<HHC;h++) s[h]=0.f;
    #pragma unroll
    for (int j=0;j<12;j++){
        int e = lane + j*32;
        float xv = siluf(proj[(size_t)row*768 + e]);
        #pragma unroll
        for (int h=0;h<HHC;h++) s[h] = fmaf(xv, wst[h*EC+e], s[h]);
    }
    #pragma unroll
    for (int h=0;h<HHC;h++){
        #pragma unroll
        for (int off=16; off>=1; off>>=1) s[h] += __shfl_xor_sync(0xffffffffu, s[h], off);
    }
    #pragma unroll
    for (int h=0;h<HHC;h++)
        if (lane == h) dtr[(size_t)row*HHC + h] = s[h];
}

// ---------------- dt path: softplus, r, cumsum (precise exp) ----------------
__global__ void k_dtscan(const float* __restrict__ dtr, const float* __restrict__ dt_bias,
                         const float* __restrict__ A_log,
                         float* __restrict__ dtb, float* __restrict__ rb, float* __restrict__ cumb){
    int k = blockIdx.x / HHC, h = blockIdx.x % HHC;
    __shared__ float part[256];
    float expA = expf(A_log[h]);
    float bias = dt_bias[h];
    int tid = threadIdx.x;
    int tbase = tid*9;
    float loc[9]; float s = 0.f;
    #pragma unroll
    for (int i=0;i<9;i++){
        size_t row = (size_t)k*LSEQ + tbase + i;
        float v  = dtr[row*HHC + h] + bias;
        float dt = (v > 20.f) ? v : log1pf(expf(v));
        dtb[row*HHC+h] = 0.5f*dt;
        rb [row*HHC+h] = expf(-dt*expA);
        s += dt; loc[i] = s;
    }
    part[tid] = s; __syncthreads();
    for (int off=1; off<256; off<<=1){
        float add = (tid >= off) ? part[tid-off] : 0.f;
        __syncthreads();
        part[tid] += add;
        __syncthreads();
    }
    float offset = part[tid] - s;
    #pragma unroll
    for (int i=0;i<9;i++){
        size_t row = (size_t)k*LSEQ + tbase + i;
        cumb[row*HHC+h] = loc[i] + offset;
    }
}

// ---------------- rms(B/C) + rotary: warp per row, compact bc input ----------------
__global__ __launch_bounds__(256) void k_rot(const float* __restrict__ bcb, const float* __restrict__ bias_bc,
                                             const float* __restrict__ theta, const float* __restrict__ cumb,
                                             float* __restrict__ Bt, float* __restrict__ Ct){
    int row  = (blockIdx.x*blockDim.x + threadIdx.x) >> 5;
    int lane = threadIdx.x & 31;
    if (row >= ROWS) return;
    float bc = bcb[(size_t)row*32 + lane] + bias_bc[lane];
    float s = bc*bc;
    s += __shfl_xor_sync(0xffffffffu, s, 1);
    s += __shfl_xor_sync(0xffffffffu, s, 2);
    s += __shfl_xor_sync(0xffffffffu, s, 4);
    s += __shfl_xor_sync(0xffffffffu, s, 8);
    float rn = rsqrtf(s*(1.f/16.f) + 1e-6f);
    float v = bc * rn;
    int j = lane & 15;
    int half = lane & 16;
    int i = j >> 1;
    float v0 = __shfl_sync(0xffffffffu, v, half + 2*i);
    float v1 = __shfl_sync(0xffffffffu, v, half + 2*i + 1);
    bool odd = (j & 1) != 0;
    #pragma unroll
    for (int h=0; h<HHC; h++){
        float cd = cumb[(size_t)row*HHC + h];
        float th = theta[h*8 + i];
        float ss, cc;
        sincosf(cd*th, &ss, &cc);
        float o = odd ? fmaf(-v0, ss, v1*cc) : fmaf(v0, cc, v1*ss);
        float* dst = half ? Ct : Bt;
        dst[((size_t)row*HHC + h)*16 + j] = o;
    }
}

// ---------------- scan phase A: per-segment local scan (h_in = 0) ----------------
#define SCH 32
__global__ __launch_bounds__(256) void k_scanA(const float* __restrict__ Bt, const float* __restrict__ Ct,
                                               const float* __restrict__ xh, const float* __restrict__ dtb,
                                               const float* __restrict__ rb, const float* __restrict__ Dsk,
                                               float* __restrict__ y, float* __restrict__ rc,
                                               float* __restrict__ hend){
    __shared__ __align__(16) float Bs[2][SCH][16];
    __shared__ __align__(16) float Cs[2][SCH][16];
    __shared__ __align__(16) float Xs[2][SCH][64];
    __shared__ float Ds[2][SCH];
    __shared__ float Rs[2][SCH];
    __shared__ __align__(16) float Ys[SCH][64];
    __shared__ float Rys[SCH];

    int kh = blockIdx.x; int k = kh/HHC, h = kh%HHC;
    int seg = blockIdx.y;
    int tseg0 = seg*TSEG;
    int tid = threadIdx.x;
    int p = tid>>2, ng = tid&3;
    size_t bBase = ((size_t)k*LSEQ*HHC + h)*16;
    size_t xBase = (size_t)k*LSEQ*EC + (size_t)h*64;
    size_t sBase = (size_t)k*LSEQ*HHC + h;
    float dsk = Dsk[h];
    float* ybase = y + (size_t)k*LSEQ*EC + h*64;
    size_t rcBase = (size_t)kh*LSEQ;

    auto stage = [&](int buf, int t0){
        {
            int id = tid & 127;
            int tl = id>>2, sg = id&3;
            size_t off = bBase + (size_t)(t0+tl)*96 + sg*4;
            if (tid < 128){
                uint32_t d = (uint32_t)__cvta_generic_to_shared(&Bs[buf][tl][sg*4]);
                CP16(d, &Bt[off]);
            } else {
                uint32_t d = (uint32_t)__cvta_generic_to_shared(&Cs[buf][tl][sg*4]);
                CP16(d, &Ct[off]);
            }
        }
        #pragma unroll
        for (int j=0;j<2;j++){
            int i = tid + j*256;
            int tl = i>>4, c = i&15;
            uint32_t d = (uint32_t)__cvta_generic_to_shared(&Xs[buf][tl][c*4]);
            CP16(d, &xh[xBase + (size_t)(t0+tl)*EC + c*4]);
        }
        if (tid < SCH){
            uint32_t d = (uint32_t)__cvta_generic_to_shared(&Ds[buf][tid]);
            CP4(d, &dtb[sBase + (size_t)(t0+tid)*HHC]);
        } else if (tid < 2*SCH){
            int tl = tid - SCH;
            uint32_t d = (uint32_t)__cvta_generic_to_shared(&Rs[buf][tl]);
            CP4(d, &rb[sBase + (size_t)(t0+tl)*HHC]);
        }
        CPCOMMIT();
    };

    float hs0=0.f,hs1=0.f,hs2=0.f,hs3=0.f;
    float bx0=0.f,bx1=0.f,bx2=0.f,bx3=0.f;
    if (seg > 0){
        int tp = tseg0 - 1;
        float4 Bp = *(const float4*)&Bt[bBase + (size_t)tp*96 + ng*4];
        float xp = xh[xBase + (size_t)tp*EC + p];
        bx0 = Bp.x*xp; bx1 = Bp.y*xp; bx2 = Bp.z*xp; bx3 = Bp.w*xp;
    }
    float rp = 1.f;

    stage(0, tseg0);
    const int NCHUNK = TSEG/SCH;   // 9
    for (int c=0; c<NCHUNK; ++c){
        int buf = c&1;
        if (c+1 < NCHUNK) stage(buf^1, tseg0 + (c+1)*SCH);
        else CPCOMMIT();
        CPWAIT1();
        __syncthreads();

        #pragma unroll 4
        for (int t=0; t<SCH; ++t){
            float4 Bv = *(const float4*)&Bs[buf][t][ng*4];
            float4 Cv = *(const float4*)&Cs[buf][t][ng*4];
            float xv = Xs[buf][t][p];
            float ad = Ds[buf][t];
            float rv = Rs[buf][t];
            float G0 = Bv.x*xv, G1 = Bv.y*xv, G2 = Bv.z*xv, G3 = Bv.w*xv;
            float u0 = fmaf(rv,bx0,G0), u1 = fmaf(rv,bx1,G1);
            float u2 = fmaf(rv,bx2,G2), u3 = fmaf(rv,bx3,G3);
            hs0 = fmaf(rv,hs0,ad*u0); hs1 = fmaf(rv,hs1,ad*u1);
            hs2 = fmaf(rv,hs2,ad*u2); hs3 = fmaf(rv,hs3,ad*u3);
            bx0=G0; bx1=G1; bx2=G2; bx3=G3;
            rp *= rv;
            float v = fmaf(Cv.x,hs0, fmaf(Cv.y,hs1, fmaf(Cv.z,hs2, Cv.w*hs3)));
            v += __shfl_xor_sync(0xffffffffu, v, 1);
            v += __shfl_xor_sync(0xffffffffu, v, 2);
            if (ng == 0) Ys[t][p] = fmaf(dsk, xv, v);
            if (tid == 0) Rys[t] = rp;
        }
        __syncthreads();
        int t0 = tseg0 + c*SCH;
        #pragma unroll
        for (int j=0;j<2;j++){
            int i = tid + j*256;
            int tl = i>>4, cc = i&15;
            *(float4*)&ybase[(size_t)(t0+tl)*EC + cc*4] = *(const float4*)&Ys[tl][cc*4];
        }
        if (tid < SCH) rc[rcBase + t0 + tid] = Rys[tid];
    }
    float4 he = make_float4(hs0,hs1,hs2,hs3);
    *(float4*)&hend[(((size_t)kh*NSEG + seg)*PC + p)*NC + ng*4] = he;
}

// ---------------- scan phase B ----------------
__global__ __launch_bounds__(256) void k_scanB(const float* __restrict__ hend,
                                               const float* __restrict__ rc,
                                               float* __restrict__ hin){
    int kh = blockIdx.x;
    int tid = threadIdx.x;
    int p = tid>>2, ng = tid&3;
    float4 hi = make_float4(0.f,0.f,0.f,0.f);
    #pragma unroll
    for (int s=0; s<NSEG; ++s){
        size_t idx = (((size_t)kh*NSEG + s)*PC + p)*NC + ng*4;
        *(float4*)&hin[idx] = hi;
        float4 he = *(const float4*)&hend[idx];
        float Rseg = rc[(size_t)kh*LSEQ + s*TSEG + TSEG-1];
        hi.x = fmaf(Rseg, hi.x, he.x);
        hi.y = fmaf(Rseg, hi.y, he.y);
        hi.z = fmaf(Rseg, hi.z, he.z);
        hi.w = fmaf(Rseg, hi.w, he.w);
    }
}

// ---------------- scan phase C: fixup y += R(t) * (C_t · h_in) ----------------
__global__ __launch_bounds__(256) void k_scanC(const float* __restrict__ Ct,
                                               const float* __restrict__ rc,
                                               const float* __restrict__ hin,
                                               float* __restrict__ y){
    int seg = blockIdx.y;
    if (seg == 0) return;
    __shared__ float Hs[PC][NC+1];
    __shared__ float Cs[SCH][NC+1];
    __shared__ float Rsh[SCH];
    int kh = blockIdx.x; int k = kh/HHC, h = kh%HHC;
    int tid = threadIdx.x;
    int p = tid&63, tq = tid>>6;
    size_t hBase = ((size_t)kh*NSEG + seg)*PC*NC;
    for (int i=tid; i<PC*NC; i+=256) Hs[i>>4][i&15] = hin[hBase + i];
    __syncthreads();
    float hn[NC];
    #pragma unroll
    for (int i=0;i<NC;i++) hn[i] = Hs[p][i];

    size_t bBase = ((size_t)k*LSEQ*HHC + h)*16;
    size_t rcBase = (size_t)kh*LSEQ;
    float* ybase = y + (size_t)k*LSEQ*EC + h*64;
    int tseg0 = seg*TSEG;

    for (int c=0; c<TSEG/SCH; ++c){
        int t0 = tseg0 + c*SCH;
        for (int i=tid; i<SCH*NC; i+=256){
            int tl = i>>4, nn = i&15;
            Cs[tl][nn] = Ct[bBase + (size_t)(t0+tl)*96 + nn];
        }
        if (tid < SCH) Rsh[tid] = rc[rcBase + t0 + tid];
        __syncthreads();
        if (Rsh[0] == 0.f) break;
        #pragma unroll
        for (int jt=0; jt<SCH/4; ++jt){
            int tl = tq + jt*4;
            float R = Rsh[tl];
            if (R != 0.f){
                float corr = 0.f;
                #pragma unroll
                for (int i=0;i<NC;i++) corr = fmaf(Cs[tl][i], hn[i], corr);
                ybase[(size_t)(t0+tl)*EC + p] += R*corr;
            }
        }
        __syncthreads();
    }
}

// ---------------- g = tf32(rms(y * silu(z)) * rms_w)  (warp per row, compact z) ----------------
__global__ void k_gate(const float* __restrict__ y, const float* __restrict__ z,
                       const float* __restrict__ rms_w, float* __restrict__ g){
    int warp = (blockIdx.x*blockDim.x + threadIdx.x) >> 5;
    int lane = threadIdx.x & 31;
    if (warp >= ROWS) return;
    size_t base = (size_t)warp*EC;
    float v[12]; float s2 = 0.f;
    #pragma unroll
    for (int j=0;j<12;j++){
        int e = lane + j*32;
        float t = y[base + e] * siluf(z[base + e]);
        v[j] = t; s2 += t*t;
    }
    #pragma unroll
    for (int off=16; off>=1; off>>=1) s2 += __shfl_xor_sync(0xffffffffu, s2, off);
    float rn = rsqrtf(s2*(1.f/384.f) + 1e-6f);
    #pragma unroll
    for (int j=0;j<12;j++){
        int e = lane + j*32;
        g[base + e] = f2tf32f(v[j]*rn*rms_w[e]);
    }
}

// ---------------- fused: x_out = mo * silu(gate); merge 4 dirs -> mT (tf32) ----------------
__global__ void k_xmerge(const float* __restrict__ mo, const float* __restrict__ proj,
                         float* __restrict__ mT){
    int idx = blockIdx.x*blockDim.x + threadIdx.x;
    if (idx >= LSEQ*EC) return;
    int l = idx / EC, e = idx % EC;
    int lt = (l%48)*48 + l/48;
    int r0 = l;
    int r1 = LSEQ + lt;
    int r2 = 2*LSEQ + 2303 - l;
    int r3 = 3*LSEQ + 2303 - lt;
    float v = mo[(size_t)r0*EC+e] * siluf(proj[(size_t)r0*768 + 384 + e])
            + mo[(size_t)r1*EC+e] * siluf(proj[(size_t)r1*768 + 384 + e])
            + mo[(size_t)r2*EC+e] * siluf(proj[(size_t)r2*768 + 384 + e])
            + mo[(size_t)r3*EC+e] * siluf(proj[(size_t)r3*768 + 384 + e]);
    mT[idx] = f2tf32f(v);
}

// ---------------- LayerNorm + residual ----------------
__global__ void k_ln(const float* __restrict__ pre, const float* __restrict__ x,
                     const float* __restrict__ ln_g, const float* __restrict__ ln_b,
                     const float* __restrict__ res_scale, float* __restrict__ out){
    int warp = (blockIdx.x*blockDim.x + threadIdx.x) >> 5;
    int lane = threadIdx.x & 31;
    if (warp >= LSEQ) return;
    int l = warp;
    float v[6]; float s = 0.f;
    #pragma unroll
    for (int j=0;j<6;j++){ v[j] = pre[(size_t)l*DIMC + lane + j*32]; s += v[j]; }
    #pragma unroll
    for (int off=16; off>=1; off>>=1) s += __shfl_xor_sync(0xffffffffu, s, off);
    float mu = s*(1.f/192.f);
    float q = 0.f;
    #pragma unroll
    for (int j=0;j<6;j++){ float d = v[j]-mu; q += d*d; }
    #pragma unroll
    for (int off=16; off>=1; off>>=1) q += __shfl_xor_sync(0xffffffffu, q, off);
    float inv = rsqrtf(q*(1.f/192.f) + 1e-5f);
    float rs = res_scale[0];
    #pragma unroll
    for (int j=0;j<6;j++){
        int d = lane + j*32;
        out[(size_t)d*LSEQ + l] = x[(size_t)d*LSEQ + l]
            + rs*((v[j]-mu)*inv*ln_g[d] + ln_b[d]);
    }
}

// ---------------- launch ----------------
extern "C" void kernel_launch(void* const* d_in, const int* in_sizes, int n_in,
                              void* d_out, int out_size){
    (void)in_sizes; (void)n_in; (void)out_size;
    const float* x        = (const float*)d_in[0];
    const float* w_in     = (const float*)d_in[1];
    const float* w_zx     = (const float*)d_in[2];
    const float* w_bc     = (const float*)d_in[3];
    const float* bias_bc  = (const float*)d_in[4];
    const float* w_dt     = (const float*)d_in[5];
    const float* dt_bias  = (const float*)d_in[6];
    const float* A_log    = (const float*)d_in[7];
    const float* theta    = (const float*)d_in[8];
    const float* D_skip   = (const float*)d_in[9];
    const float* rms_w    = (const float*)d_in[10];
    const float* w_mout   = (const float*)d_in[11];
    const float* w_out    = (const float*)d_in[12];
    const float* ln_g     = (const float*)d_in[13];
    const float* ln_b     = (const float*)d_in[14];
    const float* resscale = (const float*)d_in[15];
    float* out = (float*)d_out;

    float *b_xseq,*b_proj,*b_xssmt,*b_wcomb,*b_winT,*b_wmoutT,*b_woutT;
    float *b_z,*b_xh,*b_bcb,*b_dtr,*b_dtb,*b_rb,*b_cum,*b_Bt,*b_Ct,*b_y,*b_g,*b_mo,*b_mT,*b_pre;
    float *b_rc,*b_hend,*b_hin;
    cudaGetSymbolAddress((void**)&b_xseq,  g_xseq);
    cudaGetSymbolAddress((void**)&b_proj,  g_proj);
    cudaGetSymbolAddress((void**)&b_xssmt, g_xssmt);
    cudaGetSymbolAddress((void**)&b_wcomb, g_wcomb);
    cudaGetSymbolAddress((void**)&b_winT,  g_winT);
    cudaGetSymbolAddress((void**)&b_wmoutT,g_wmoutT);
    cudaGetSymbolAddress((void**)&b_woutT, g_woutT);
    cudaGetSymbolAddress((void**)&b_z,     g_z);
    cudaGetSymbolAddress((void**)&b_xh,    g_xh);
    cudaGetSymbolAddress((void**)&b_bcb,   g_bcb);
    cudaGetSymbolAddress((void**)&b_dtr,   g_dtr);
    cudaGetSymbolAddress((void**)&b_dtb,   g_dtb);
    cudaGetSymbolAddress((void**)&b_rb,    g_rb);
    cudaGetSymbolAddress((void**)&b_cum,   g_cum);
    cudaGetSymbolAddress((void**)&b_Bt,    g_Bt);
    cudaGetSymbolAddress((void**)&b_Ct,    g_Ct);
    cudaGetSymbolAddress((void**)&b_y,     g_y);
    cudaGetSymbolAddress((void**)&b_g,     g_g);
    cudaGetSymbolAddress((void**)&b_mo,    g_mo);
    cudaGetSymbolAddress((void**)&b_mT,    g_mT);
    cudaGetSymbolAddress((void**)&b_pre,   g_pre);
    cudaGetSymbolAddress((void**)&b_rc,    g_rc);
    cudaGetSymbolAddress((void**)&b_hend,  g_hend);
    cudaGetSymbolAddress((void**)&b_hin,   g_hin);

    cudaFuncSetAttribute(k_gemm<0>, cudaFuncAttributeMaxDynamicSharedMemorySize, GEMM_SMEM);
    cudaFuncSetAttribute(k_gemm<1>, cudaFuncAttributeMaxDynamicSharedMemorySize, GEMM_SMEM);
    cudaFuncSetAttribute(k_gemm<2>, cudaFuncAttributeMaxDynamicSharedMemorySize, GEMM_SMEM);

    // 0: fused build + weight prep
    k_prep<<<PREP_BUILD_BLKS + PREP_W_BLKS, 256>>>(x, b_xseq, w_in, w_mout, w_out, w_zx, w_bc,
                                                   b_winT, b_wmoutT, b_woutT, b_wcomb);
    // 1: proj GEMM (9216x768x192) + silu epilogue -> xssmt
    k_gemm<1><<<dim3(768/128, ROWS/128), 256, GEMM_SMEM>>>(b_xseq, b_winT, b_proj, ROWS, 768, DIMC,
                                                           b_xssmt, nullptr, nullptr);
    // 2: dt GEMV (fp32)
    k_dtgemv<<<ROWS/8, 256>>>(b_proj, w_dt, b_dtr);
    // 3: zx GEMM (9216x800x384), split epilogue -> z / xh / bc
    k_gemm<2><<<dim3((ZXW+127)/128, ROWS/128), 256, GEMM_SMEM>>>(b_xssmt, b_wcomb, nullptr, ROWS, ZXW, EC,
                                                                 b_z, b_xh, b_bcb);
    // 4: dt / r / cumsum
    k_dtscan<<<KC*HHC, 256>>>(b_dtr, dt_bias, A_log, b_dtb, b_rb, b_cum);
    // 5: rms + rotary
    k_rot<<<ROWS/8, 256>>>(b_bcb, bias_bc, theta, b_cum, b_Bt, b_Ct);
    // 6: split-sequence scan
    k_scanA<<<dim3(KC*HHC, NSEG), 256>>>(b_Bt, b_Ct, b_xh, b_dtb, b_rb, D_skip, b_y, b_rc, b_hend);
    k_scanB<<<KC*HHC, 256>>>(b_hend, b_rc, b_hin);
    k_scanC<<<dim3(KC*HHC, NSEG), 256>>>(b_Ct, b_rc, b_hin, b_y);
    // 7: gated rms norm
    k_gate<<<(ROWS*32+255)/256, 256>>>(b_y, b_z, rms_w, b_g);
    // 8: mamba out GEMM (9216x384x384)
    k_gemm<0><<<dim3(EC/128, ROWS/128), 256, GEMM_SMEM>>>(b_g, b_wmoutT, b_mo, ROWS, EC, EC,
                                                          nullptr, nullptr, nullptr);
    // 9: fused gate-multiply + merge
    k_xmerge<<<(LSEQ*EC+255)/256, 256>>>(b_mo, b_proj, b_mT);
    // 10: output projection GEMM (2304x192x384)
    k_gemm<0><<<dim3((DIMC+127)/128, LSEQ/128), 256, GEMM_SMEM>>>(b_mT, b_woutT, b_pre, LSEQ, DIMC, EC,
                                                                  nullptr, nullptr, nullptr);
    // 11: layernorm + residual
    k_ln<<<(LSEQ*32+255)/256, 256>>>(b_pre, x, ln_g, ln_b, resscale, out);
}